// round 1
// baseline (speedup 1.0000x reference)
#include <cuda_runtime.h>
#include <cuda_bf16.h>
#include <math.h>
#include <stdint.h>

// Problem dims (fixed)
#define S_DIM 2048
#define N_DIM 32
#define H_DIM 1024
#define E_DIM 1024
#define M_TOTAL (S_DIM * N_DIM)   // 65536 rows, row m = s*32 + n

// GEMM tile config
#define BM 128
#define BN 128
#define BK 32
#define LDS_H 40                  // halves per smem row (32 data + 8 pad -> conflict-free ldmatrix)
#define GEMM_THREADS 256
#define GEMM_SMEM (2 * 4 * BM * LDS_H * 2)   // 81920 bytes: double-buffered Ah/Al/Bh/Bl

// ---------------- device scratch (no cudaMalloc allowed) ----------------
__device__ __nv_bfloat16 g_W2h[E_DIM * H_DIM];   // 2 MB
__device__ __nv_bfloat16 g_W2l[E_DIM * H_DIM];   // 2 MB
__device__ float g_base[N_DIM * E_DIM];          // hidden@W1^T + b1 + b2, [n][e]
__device__ float g_a[M_TOTAL];                   // logits a[s*32+n]

// ---------------- P0: split W2 to bf16 hi/lo, zero logits ----------------
__global__ void prep_kernel(const float* __restrict__ W2) {
    int idx = blockIdx.x * blockDim.x + threadIdx.x;
    int stride = gridDim.x * blockDim.x;
    for (int i = idx; i < E_DIM * H_DIM; i += stride) {
        float v = W2[i];
        __nv_bfloat16 hi = __float2bfloat16(v);
        g_W2h[i] = hi;
        g_W2l[i] = __float2bfloat16(v - __bfloat162float(hi));
    }
    for (int i = idx; i < M_TOTAL; i += stride) g_a[i] = 0.0f;
}

// ---------------- K1: base[n][e] = hidden[n]·W1[e] + b1[e] + b2[e] ----------------
__global__ void base_kernel(const float* __restrict__ hidden,
                            const float* __restrict__ W1,
                            const float* __restrict__ b1,
                            const float* __restrict__ b2) {
    int e = blockIdx.x;           // 1024 blocks
    int lane = threadIdx.x & 31;
    int w = threadIdx.x >> 5;     // 8 warps
    const float* w1row = W1 + e * H_DIM;
    float bias = b1[e] + b2[e];
    for (int n = w; n < N_DIM; n += 8) {
        const float* hrow = hidden + n * H_DIM;
        float acc = 0.0f;
        #pragma unroll 4
        for (int h = lane; h < H_DIM; h += 32) acc += hrow[h] * w1row[h];
        #pragma unroll
        for (int o = 16; o; o >>= 1) acc += __shfl_xor_sync(0xffffffffu, acc, o);
        if (lane == 0) g_base[n * E_DIM + e] = acc + bias;
    }
}

// ---------------- mma helpers ----------------
__device__ __forceinline__ void ldmx4(uint32_t* r, uint32_t addr) {
    asm volatile("ldmatrix.sync.aligned.m8n8.x4.shared.b16 {%0,%1,%2,%3}, [%4];"
                 : "=r"(r[0]), "=r"(r[1]), "=r"(r[2]), "=r"(r[3])
                 : "r"(addr));
}
__device__ __forceinline__ void mma16816(float* c, const uint32_t* a, uint32_t b0, uint32_t b1) {
    asm volatile("mma.sync.aligned.m16n8k16.row.col.f32.bf16.bf16.f32 "
                 "{%0,%1,%2,%3}, {%4,%5,%6,%7}, {%8,%9}, {%0,%1,%2,%3};"
                 : "+f"(c[0]), "+f"(c[1]), "+f"(c[2]), "+f"(c[3])
                 : "r"(a[0]), "r"(a[1]), "r"(a[2]), "r"(a[3]), "r"(b0), "r"(b1));
}

// ---------------- K2: fused GEMM + tanh + W3-dot -> atomicAdd logits ----------------
// D(m_tile, e_tile) = out_e_tile(128x1024) @ W2_tile(128x1024)^T  (K streamed in 32-chunks)
// split-bf16: acc += Ah*Bh + Ah*Bl + Al*Bh
__global__ void __launch_bounds__(GEMM_THREADS) gemm_kernel(const float* __restrict__ A,
                                                            const float* __restrict__ W3) {
    extern __shared__ char smem[];
    __nv_bfloat16* sA_h = (__nv_bfloat16*)smem;         // [2][BM*LDS_H]
    __nv_bfloat16* sA_l = sA_h + 2 * BM * LDS_H;
    __nv_bfloat16* sB_h = sA_l + 2 * BM * LDS_H;
    __nv_bfloat16* sB_l = sB_h + 2 * BM * LDS_H;

    const int tid = threadIdx.x;
    const int lane = tid & 31;
    const int wid = tid >> 5;
    const int wM = wid & 3;      // 4 warps along M (warp tile 32 rows)
    const int wN = wid >> 2;     // 2 warps along N (warp tile 64 cols)
    const int mBase = blockIdx.x * BM;
    const int eBase = blockIdx.y * BN;

    float acc[2][8][4];
    #pragma unroll
    for (int i = 0; i < 2; i++)
        #pragma unroll
        for (int j = 0; j < 8; j++)
            #pragma unroll
            for (int k = 0; k < 4; k++) acc[i][j][k] = 0.0f;

    float4 aReg[4];
    uint4 bhReg[2], blReg[2];

    auto g2r = [&](int kt) {
        int k0 = kt * BK;
        #pragma unroll
        for (int i = 0; i < 4; i++) {
            int idx = i * 256 + tid, r = idx >> 3, c = idx & 7;
            aReg[i] = *(const float4*)(A + (size_t)(mBase + r) * H_DIM + k0 + c * 4);
        }
        #pragma unroll
        for (int i = 0; i < 2; i++) {
            int idx = i * 256 + tid, r = idx >> 2, c = idx & 3;
            size_t off = (size_t)(eBase + r) * H_DIM + k0 + c * 8;
            bhReg[i] = *(const uint4*)(g_W2h + off);
            blReg[i] = *(const uint4*)(g_W2l + off);
        }
    };
    auto r2s = [&](int buf) {
        #pragma unroll
        for (int i = 0; i < 4; i++) {
            int idx = i * 256 + tid, r = idx >> 3, c = idx & 7;
            int off = buf * BM * LDS_H + r * LDS_H + c * 4;
            float4 v = aReg[i];
            __nv_bfloat16 h0 = __float2bfloat16(v.x);
            __nv_bfloat16 h1 = __float2bfloat16(v.y);
            __nv_bfloat16 h2 = __float2bfloat16(v.z);
            __nv_bfloat16 h3 = __float2bfloat16(v.w);
            *(__nv_bfloat162*)(sA_h + off)     = __halves2bfloat162(h0, h1);
            *(__nv_bfloat162*)(sA_h + off + 2) = __halves2bfloat162(h2, h3);
            __nv_bfloat16 l0 = __float2bfloat16(v.x - __bfloat162float(h0));
            __nv_bfloat16 l1 = __float2bfloat16(v.y - __bfloat162float(h1));
            __nv_bfloat16 l2 = __float2bfloat16(v.z - __bfloat162float(h2));
            __nv_bfloat16 l3 = __float2bfloat16(v.w - __bfloat162float(h3));
            *(__nv_bfloat162*)(sA_l + off)     = __halves2bfloat162(l0, l1);
            *(__nv_bfloat162*)(sA_l + off + 2) = __halves2bfloat162(l2, l3);
        }
        #pragma unroll
        for (int i = 0; i < 2; i++) {
            int idx = i * 256 + tid, r = idx >> 2, c = idx & 3;
            int off = buf * BM * LDS_H + r * LDS_H + c * 8;
            *(uint4*)(sB_h + off) = bhReg[i];
            *(uint4*)(sB_l + off) = blReg[i];
        }
    };
    auto compute = [&](int buf) {
        uint32_t baseAh = (uint32_t)__cvta_generic_to_shared(sA_h + buf * BM * LDS_H);
        uint32_t baseAl = (uint32_t)__cvta_generic_to_shared(sA_l + buf * BM * LDS_H);
        uint32_t baseBh = (uint32_t)__cvta_generic_to_shared(sB_h + buf * BM * LDS_H);
        uint32_t baseBl = (uint32_t)__cvta_generic_to_shared(sB_l + buf * BM * LDS_H);
        uint32_t ah[2][2][4], al[2][2][4];
        #pragma unroll
        for (int mt = 0; mt < 2; mt++)
            #pragma unroll
            for (int ks = 0; ks < 2; ks++) {
                int row = wM * 32 + mt * 16 + (lane & 15);
                uint32_t off = row * (LDS_H * 2) + ks * 32 + ((lane >> 4) * 16);
                ldmx4(ah[mt][ks], baseAh + off);
                ldmx4(al[mt][ks], baseAl + off);
            }
        #pragma unroll
        for (int nt = 0; nt < 8; nt++) {
            uint32_t bh[4], bl[4];
            int row = wN * 64 + nt * 8 + (lane & 7);
            uint32_t off = row * (LDS_H * 2) + ((lane >> 3) * 16);
            ldmx4(bh, baseBh + off);
            ldmx4(bl, baseBl + off);
            #pragma unroll
            for (int mt = 0; mt < 2; mt++) {
                mma16816(acc[mt][nt], ah[mt][0], bh[0], bh[1]);  // ks0 hi*hi
                mma16816(acc[mt][nt], ah[mt][1], bh[2], bh[3]);  // ks1 hi*hi
                mma16816(acc[mt][nt], ah[mt][0], bl[0], bl[1]);  // hi*lo
                mma16816(acc[mt][nt], ah[mt][1], bl[2], bl[3]);
                mma16816(acc[mt][nt], al[mt][0], bh[0], bh[1]);  // lo*hi
                mma16816(acc[mt][nt], al[mt][1], bh[2], bh[3]);
            }
        }
    };

    const int NK = H_DIM / BK;   // 32
    g2r(0);
    r2s(0);
    __syncthreads();
    for (int kt = 0; kt < NK; ++kt) {
        int buf = kt & 1;
        if (kt + 1 < NK) g2r(kt + 1);
        compute(buf);
        if (kt + 1 < NK) r2s(buf ^ 1);
        __syncthreads();
    }

    // ---- epilogue: a_partial[m] = sum_e W3[e]*tanh(acc + base[n][e]) ----
    float* sBase = (float*)smem;           // [32][136] (pad 136 avoids quad conflicts)
    float* sW3 = sBase + 32 * 136;
    for (int idx = tid; idx < 32 * 128; idx += GEMM_THREADS) {
        int n = idx >> 7, el = idx & 127;
        sBase[n * 136 + el] = g_base[n * E_DIM + eBase + el];
    }
    if (tid < 128) sW3[tid] = W3[eBase + tid];
    __syncthreads();

    #pragma unroll
    for (int mt = 0; mt < 2; mt++)
        #pragma unroll
        for (int rp = 0; rp < 2; rp++) {
            int rloc = wM * 32 + mt * 16 + rp * 8 + (lane >> 2);
            int n = rloc & 31;           // mBase multiple of 128 -> n = m % 32
            float part = 0.0f;
            #pragma unroll
            for (int nt = 0; nt < 8; nt++) {
                int el = wN * 64 + nt * 8 + ((lane & 3) << 1);
                float p0 = acc[mt][nt][rp * 2 + 0] + sBase[n * 136 + el];
                float p1 = acc[mt][nt][rp * 2 + 1] + sBase[n * 136 + el + 1];
                part += sW3[el] * tanhf(p0) + sW3[el + 1] * tanhf(p1);
            }
            part += __shfl_xor_sync(0xffffffffu, part, 1);
            part += __shfl_xor_sync(0xffffffffu, part, 2);
            if ((lane & 3) == 0) atomicAdd(&g_a[mBase + rloc], part);
        }
}

// ---------------- K3: softmax over S per n; also zeroes context region ----------------
__global__ void softmax_kernel(float* __restrict__ alpha, float* __restrict__ c) {
    int n = blockIdx.x;                 // 32 blocks
    int tid = threadIdx.x;              // 256
    ((float4*)(c + n * H_DIM))[tid] = make_float4(0.f, 0.f, 0.f, 0.f);

    float v[8];
    float mx = -1e30f;
    #pragma unroll
    for (int i = 0; i < 8; i++) {
        v[i] = g_a[(i * 256 + tid) * N_DIM + n];
        mx = fmaxf(mx, v[i]);
    }
    #pragma unroll
    for (int o = 16; o; o >>= 1) mx = fmaxf(mx, __shfl_xor_sync(0xffffffffu, mx, o));
    __shared__ float sm[8];
    if ((tid & 31) == 0) sm[tid >> 5] = mx;
    __syncthreads();
    float bmax = fmaxf(fmaxf(fmaxf(sm[0], sm[1]), fmaxf(sm[2], sm[3])),
                       fmaxf(fmaxf(sm[4], sm[5]), fmaxf(sm[6], sm[7])));
    float sum = 0.0f;
    #pragma unroll
    for (int i = 0; i < 8; i++) {
        v[i] = expf(v[i] - bmax);
        sum += v[i];
    }
    #pragma unroll
    for (int o = 16; o; o >>= 1) sum += __shfl_xor_sync(0xffffffffu, sum, o);
    __syncthreads();
    if ((tid & 31) == 0) sm[tid >> 5] = sum;
    __syncthreads();
    float tot = sm[0] + sm[1] + sm[2] + sm[3] + sm[4] + sm[5] + sm[6] + sm[7];
    float inv = 1.0f / tot;
    #pragma unroll
    for (int i = 0; i < 8; i++)
        alpha[(i * 256 + tid) * N_DIM + n] = v[i] * inv;
}

// ---------------- K4: c[n][h] = sum_s alpha[s,n]*out_e[s,n,h] ----------------
__global__ void context_kernel(const float* __restrict__ out_e,
                               const float* __restrict__ alpha,
                               float* __restrict__ c) {
    int n = blockIdx.x;                  // 32
    int sc = blockIdx.y;                 // 16 s-chunks of 128
    int tid = threadIdx.x;               // 256; each thread one float4 of H
    const float4* p = (const float4*)out_e + (size_t)n * (H_DIM / 4) + tid;
    const size_t srow = (size_t)N_DIM * H_DIM / 4;
    int s0 = sc * 128;
    float4 acc = make_float4(0.f, 0.f, 0.f, 0.f);
    #pragma unroll 4
    for (int s = s0; s < s0 + 128; ++s) {
        float al = alpha[s * N_DIM + n];
        float4 x = p[s * srow];
        acc.x += al * x.x; acc.y += al * x.y; acc.z += al * x.z; acc.w += al * x.w;
    }
    float* dst = c + n * H_DIM + tid * 4;
    atomicAdd(dst + 0, acc.x);
    atomicAdd(dst + 1, acc.y);
    atomicAdd(dst + 2, acc.z);
    atomicAdd(dst + 3, acc.w);
}

// ---------------- launch ----------------
extern "C" void kernel_launch(void* const* d_in, const int* in_sizes, int n_in,
                              void* d_out, int out_size) {
    const float* out_e  = (const float*)d_in[0];
    const float* hidden = (const float*)d_in[1];
    const float* W1     = (const float*)d_in[2];
    const float* b1     = (const float*)d_in[3];
    const float* W2     = (const float*)d_in[4];
    const float* b2     = (const float*)d_in[5];
    const float* W3     = (const float*)d_in[6];
    // b3 (d_in[7]) shifts all logits equally -> softmax-invariant -> unused.

    float* out = (float*)d_out;          // [0,32768): c (1,N,H); [32768,98304): alpha (S,N,1)
    float* c_out = out;
    float* alpha_out = out + N_DIM * H_DIM;

    static int smem_set = 0;
    if (!smem_set) {
        cudaFuncSetAttribute(gemm_kernel, cudaFuncAttributeMaxDynamicSharedMemorySize, GEMM_SMEM);
        smem_set = 1;
    }

    prep_kernel<<<512, 256>>>(W2);
    base_kernel<<<E_DIM, 256>>>(hidden, W1, b1, b2);
    gemm_kernel<<<dim3(M_TOTAL / BM, E_DIM / BN), GEMM_THREADS, GEMM_SMEM>>>(out_e, W3);
    softmax_kernel<<<N_DIM, 256>>>(alpha_out, c_out);
    context_kernel<<<dim3(N_DIM, 16), 256>>>(out_e, alpha_out, c_out);
}

// round 3
// speedup vs baseline: 1.0002x; 1.0002x over previous
#include <cuda_runtime.h>
#include <cuda_bf16.h>
#include <math.h>
#include <stdint.h>

// Problem dims (fixed)
#define S_DIM 2048
#define N_DIM 32
#define H_DIM 1024
#define E_DIM 1024
#define M_TOTAL (S_DIM * N_DIM)   // 65536 rows, row m = s*32 + n

// GEMM tile config
#define BM 128
#define BN 128
#define BK 32
#define LDS_H 40                  // halves per smem row (32 data + 8 pad -> conflict-free ldmatrix)
#define GEMM_THREADS 256
#define GEMM_SMEM (2 * 4 * BM * LDS_H * 2)   // 81920 bytes: double-buffered Ah/Al/Bh/Bl

// ---------------- device scratch (no cudaMalloc allowed) ----------------
__device__ __nv_bfloat16 g_W2h[E_DIM * H_DIM];   // 2 MB
__device__ __nv_bfloat16 g_W2l[E_DIM * H_DIM];   // 2 MB
__device__ float g_base[N_DIM * E_DIM];          // hidden@W1^T + b1 + b2, [n][e]
__device__ float g_a[M_TOTAL];                   // logits a[s*32+n]

// ---------------- P0: split W2 to bf16 hi/lo, zero logits ----------------
__global__ void prep_kernel(const float* __restrict__ W2) {
    int idx = blockIdx.x * blockDim.x + threadIdx.x;
    int stride = gridDim.x * blockDim.x;
    for (int i = idx; i < E_DIM * H_DIM; i += stride) {
        float v = W2[i];
        __nv_bfloat16 hi = __float2bfloat16(v);
        g_W2h[i] = hi;
        g_W2l[i] = __float2bfloat16(v - __bfloat162float(hi));
    }
    for (int i = idx; i < M_TOTAL; i += stride) g_a[i] = 0.0f;
}

// ---------------- K1: base[n][e] = hidden[n]·W1[e] + b1[e] + b2[e] ----------------
__global__ void base_kernel(const float* __restrict__ hidden,
                            const float* __restrict__ W1,
                            const float* __restrict__ b1,
                            const float* __restrict__ b2) {
    int e = blockIdx.x;           // 1024 blocks
    int lane = threadIdx.x & 31;
    int w = threadIdx.x >> 5;     // 8 warps
    const float* w1row = W1 + e * H_DIM;
    float bias = b1[e] + b2[e];
    for (int n = w; n < N_DIM; n += 8) {
        const float* hrow = hidden + n * H_DIM;
        float acc = 0.0f;
        #pragma unroll 4
        for (int h = lane; h < H_DIM; h += 32) acc += hrow[h] * w1row[h];
        #pragma unroll
        for (int o = 16; o; o >>= 1) acc += __shfl_xor_sync(0xffffffffu, acc, o);
        if (lane == 0) g_base[n * E_DIM + e] = acc + bias;
    }
}

// ---------------- mma helpers ----------------
__device__ __forceinline__ void ldmx4(uint32_t* r, uint32_t addr) {
    asm volatile("ldmatrix.sync.aligned.m8n8.x4.shared.b16 {%0,%1,%2,%3}, [%4];"
                 : "=r"(r[0]), "=r"(r[1]), "=r"(r[2]), "=r"(r[3])
                 : "r"(addr));
}
__device__ __forceinline__ void mma16816(float* c, const uint32_t* a, uint32_t b0, uint32_t b1) {
    asm volatile("mma.sync.aligned.m16n8k16.row.col.f32.bf16.bf16.f32 "
                 "{%0,%1,%2,%3}, {%4,%5,%6,%7}, {%8,%9}, {%0,%1,%2,%3};"
                 : "+f"(c[0]), "+f"(c[1]), "+f"(c[2]), "+f"(c[3])
                 : "r"(a[0]), "r"(a[1]), "r"(a[2]), "r"(a[3]), "r"(b0), "r"(b1));
}

// ---------------- K2: fused GEMM + tanh + W3-dot -> atomicAdd logits ----------------
// D(m_tile, e_tile) = out_e_tile(128x1024) @ W2_tile(128x1024)^T  (K streamed in 32-chunks)
// split-bf16: acc += Ah*Bh + Ah*Bl + Al*Bh
__global__ void __launch_bounds__(GEMM_THREADS) gemm_kernel(const float* __restrict__ A,
                                                            const float* __restrict__ W3) {
    extern __shared__ char smem[];
    __nv_bfloat16* sA_h = (__nv_bfloat16*)smem;         // [2][BM*LDS_H]
    __nv_bfloat16* sA_l = sA_h + 2 * BM * LDS_H;
    __nv_bfloat16* sB_h = sA_l + 2 * BM * LDS_H;
    __nv_bfloat16* sB_l = sB_h + 2 * BM * LDS_H;

    const int tid = threadIdx.x;
    const int lane = tid & 31;
    const int wid = tid >> 5;
    const int wM = wid & 3;      // 4 warps along M (warp tile 32 rows)
    const int wN = wid >> 2;     // 2 warps along N (warp tile 64 cols)
    const int mBase = blockIdx.x * BM;
    const int eBase = blockIdx.y * BN;

    float acc[2][8][4];
    #pragma unroll
    for (int i = 0; i < 2; i++)
        #pragma unroll
        for (int j = 0; j < 8; j++)
            #pragma unroll
            for (int k = 0; k < 4; k++) acc[i][j][k] = 0.0f;

    float4 aReg[4];
    uint4 bhReg[2], blReg[2];

    auto g2r = [&](int kt) {
        int k0 = kt * BK;
        #pragma unroll
        for (int i = 0; i < 4; i++) {
            int idx = i * 256 + tid, r = idx >> 3, c = idx & 7;
            aReg[i] = *(const float4*)(A + (size_t)(mBase + r) * H_DIM + k0 + c * 4);
        }
        #pragma unroll
        for (int i = 0; i < 2; i++) {
            int idx = i * 256 + tid, r = idx >> 2, c = idx & 3;
            size_t off = (size_t)(eBase + r) * H_DIM + k0 + c * 8;
            bhReg[i] = *(const uint4*)(g_W2h + off);
            blReg[i] = *(const uint4*)(g_W2l + off);
        }
    };
    auto r2s = [&](int buf) {
        #pragma unroll
        for (int i = 0; i < 4; i++) {
            int idx = i * 256 + tid, r = idx >> 3, c = idx & 7;
            int off = buf * BM * LDS_H + r * LDS_H + c * 4;
            float4 v = aReg[i];
            __nv_bfloat16 h0 = __float2bfloat16(v.x);
            __nv_bfloat16 h1 = __float2bfloat16(v.y);
            __nv_bfloat16 h2 = __float2bfloat16(v.z);
            __nv_bfloat16 h3 = __float2bfloat16(v.w);
            *(__nv_bfloat162*)(sA_h + off)     = __halves2bfloat162(h0, h1);
            *(__nv_bfloat162*)(sA_h + off + 2) = __halves2bfloat162(h2, h3);
            __nv_bfloat16 l0 = __float2bfloat16(v.x - __bfloat162float(h0));
            __nv_bfloat16 l1 = __float2bfloat16(v.y - __bfloat162float(h1));
            __nv_bfloat16 l2 = __float2bfloat16(v.z - __bfloat162float(h2));
            __nv_bfloat16 l3 = __float2bfloat16(v.w - __bfloat162float(h3));
            *(__nv_bfloat162*)(sA_l + off)     = __halves2bfloat162(l0, l1);
            *(__nv_bfloat162*)(sA_l + off + 2) = __halves2bfloat162(l2, l3);
        }
        #pragma unroll
        for (int i = 0; i < 2; i++) {
            int idx = i * 256 + tid, r = idx >> 2, c = idx & 3;
            int off = buf * BM * LDS_H + r * LDS_H + c * 8;
            *(uint4*)(sB_h + off) = bhReg[i];
            *(uint4*)(sB_l + off) = blReg[i];
        }
    };
    auto compute = [&](int buf) {
        uint32_t baseAh = (uint32_t)__cvta_generic_to_shared(sA_h + buf * BM * LDS_H);
        uint32_t baseAl = (uint32_t)__cvta_generic_to_shared(sA_l + buf * BM * LDS_H);
        uint32_t baseBh = (uint32_t)__cvta_generic_to_shared(sB_h + buf * BM * LDS_H);
        uint32_t baseBl = (uint32_t)__cvta_generic_to_shared(sB_l + buf * BM * LDS_H);
        uint32_t ah[2][2][4], al[2][2][4];
        #pragma unroll
        for (int mt = 0; mt < 2; mt++)
            #pragma unroll
            for (int ks = 0; ks < 2; ks++) {
                int row = wM * 32 + mt * 16 + (lane & 15);
                uint32_t off = row * (LDS_H * 2) + ks * 32 + ((lane >> 4) * 16);
                ldmx4(ah[mt][ks], baseAh + off);
                ldmx4(al[mt][ks], baseAl + off);
            }
        #pragma unroll
        for (int nt = 0; nt < 8; nt++) {
            uint32_t bh[4], bl[4];
            int row = wN * 64 + nt * 8 + (lane & 7);
            uint32_t off = row * (LDS_H * 2) + ((lane >> 3) * 16);
            ldmx4(bh, baseBh + off);
            ldmx4(bl, baseBl + off);
            #pragma unroll
            for (int mt = 0; mt < 2; mt++) {
                mma16816(acc[mt][nt], ah[mt][0], bh[0], bh[1]);  // ks0 hi*hi
                mma16816(acc[mt][nt], ah[mt][1], bh[2], bh[3]);  // ks1 hi*hi
                mma16816(acc[mt][nt], ah[mt][0], bl[0], bl[1]);  // hi*lo
                mma16816(acc[mt][nt], ah[mt][1], bl[2], bl[3]);
                mma16816(acc[mt][nt], al[mt][0], bh[0], bh[1]);  // lo*hi
                mma16816(acc[mt][nt], al[mt][1], bh[2], bh[3]);
            }
        }
    };

    const int NK = H_DIM / BK;   // 32
    g2r(0);
    r2s(0);
    __syncthreads();
    for (int kt = 0; kt < NK; ++kt) {
        int buf = kt & 1;
        if (kt + 1 < NK) g2r(kt + 1);
        compute(buf);
        if (kt + 1 < NK) r2s(buf ^ 1);
        __syncthreads();
    }

    // ---- epilogue: a_partial[m] = sum_e W3[e]*tanh(acc + base[n][e]) ----
    float* sBase = (float*)smem;           // [32][136] (pad 136 avoids quad conflicts)
    float* sW3 = sBase + 32 * 136;
    for (int idx = tid; idx < 32 * 128; idx += GEMM_THREADS) {
        int n = idx >> 7, el = idx & 127;
        sBase[n * 136 + el] = g_base[n * E_DIM + eBase + el];
    }
    if (tid < 128) sW3[tid] = W3[eBase + tid];
    __syncthreads();

    #pragma unroll
    for (int mt = 0; mt < 2; mt++)
        #pragma unroll
        for (int rp = 0; rp < 2; rp++) {
            int rloc = wM * 32 + mt * 16 + rp * 8 + (lane >> 2);
            int n = rloc & 31;           // mBase multiple of 128 -> n = m % 32
            float part = 0.0f;
            #pragma unroll
            for (int nt = 0; nt < 8; nt++) {
                int el = wN * 64 + nt * 8 + ((lane & 3) << 1);
                float p0 = acc[mt][nt][rp * 2 + 0] + sBase[n * 136 + el];
                float p1 = acc[mt][nt][rp * 2 + 1] + sBase[n * 136 + el + 1];
                part += sW3[el] * tanhf(p0) + sW3[el + 1] * tanhf(p1);
            }
            part += __shfl_xor_sync(0xffffffffu, part, 1);
            part += __shfl_xor_sync(0xffffffffu, part, 2);
            if ((lane & 3) == 0) atomicAdd(&g_a[mBase + rloc], part);
        }
}

// ---------------- K3: softmax over S per n; also zeroes context region ----------------
__global__ void softmax_kernel(float* __restrict__ alpha, float* __restrict__ c) {
    int n = blockIdx.x;                 // 32 blocks
    int tid = threadIdx.x;              // 256
    ((float4*)(c + n * H_DIM))[tid] = make_float4(0.f, 0.f, 0.f, 0.f);

    float v[8];
    float mx = -1e30f;
    #pragma unroll
    for (int i = 0; i < 8; i++) {
        v[i] = g_a[(i * 256 + tid) * N_DIM + n];
        mx = fmaxf(mx, v[i]);
    }
    #pragma unroll
    for (int o = 16; o; o >>= 1) mx = fmaxf(mx, __shfl_xor_sync(0xffffffffu, mx, o));
    __shared__ float sm[8];
    if ((tid & 31) == 0) sm[tid >> 5] = mx;
    __syncthreads();
    float bmax = fmaxf(fmaxf(fmaxf(sm[0], sm[1]), fmaxf(sm[2], sm[3])),
                       fmaxf(fmaxf(sm[4], sm[5]), fmaxf(sm[6], sm[7])));
    float sum = 0.0f;
    #pragma unroll
    for (int i = 0; i < 8; i++) {
        v[i] = expf(v[i] - bmax);
        sum += v[i];
    }
    #pragma unroll
    for (int o = 16; o; o >>= 1) sum += __shfl_xor_sync(0xffffffffu, sum, o);
    __syncthreads();
    if ((tid & 31) == 0) sm[tid >> 5] = sum;
    __syncthreads();
    float tot = sm[0] + sm[1] + sm[2] + sm[3] + sm[4] + sm[5] + sm[6] + sm[7];
    float inv = 1.0f / tot;
    #pragma unroll
    for (int i = 0; i < 8; i++)
        alpha[(i * 256 + tid) * N_DIM + n] = v[i] * inv;
}

// ---------------- K4: c[n][h] = sum_s alpha[s,n]*out_e[s,n,h] ----------------
__global__ void context_kernel(const float* __restrict__ out_e,
                               const float* __restrict__ alpha,
                               float* __restrict__ c) {
    int n = blockIdx.x;                  // 32
    int sc = blockIdx.y;                 // 16 s-chunks of 128
    int tid = threadIdx.x;               // 256; each thread one float4 of H
    const float4* p = (const float4*)out_e + (size_t)n * (H_DIM / 4) + tid;
    const size_t srow = (size_t)N_DIM * H_DIM / 4;
    int s0 = sc * 128;
    float4 acc = make_float4(0.f, 0.f, 0.f, 0.f);
    #pragma unroll 4
    for (int s = s0; s < s0 + 128; ++s) {
        float al = alpha[s * N_DIM + n];
        float4 x = p[s * srow];
        acc.x += al * x.x; acc.y += al * x.y; acc.z += al * x.z; acc.w += al * x.w;
    }
    float* dst = c + n * H_DIM + tid * 4;
    atomicAdd(dst + 0, acc.x);
    atomicAdd(dst + 1, acc.y);
    atomicAdd(dst + 2, acc.z);
    atomicAdd(dst + 3, acc.w);
}

// ---------------- launch ----------------
extern "C" void kernel_launch(void* const* d_in, const int* in_sizes, int n_in,
                              void* d_out, int out_size) {
    const float* out_e  = (const float*)d_in[0];
    const float* hidden = (const float*)d_in[1];
    const float* W1     = (const float*)d_in[2];
    const float* b1     = (const float*)d_in[3];
    const float* W2     = (const float*)d_in[4];
    const float* b2     = (const float*)d_in[5];
    const float* W3     = (const float*)d_in[6];
    // b3 (d_in[7]) shifts all logits equally -> softmax-invariant -> unused.

    float* out = (float*)d_out;          // [0,32768): c (1,N,H); [32768,98304): alpha (S,N,1)
    float* c_out = out;
    float* alpha_out = out + N_DIM * H_DIM;

    static int smem_set = 0;
    if (!smem_set) {
        cudaFuncSetAttribute(gemm_kernel, cudaFuncAttributeMaxDynamicSharedMemorySize, GEMM_SMEM);
        smem_set = 1;
    }

    prep_kernel<<<512, 256>>>(W2);
    base_kernel<<<E_DIM, 256>>>(hidden, W1, b1, b2);
    gemm_kernel<<<dim3(M_TOTAL / BM, E_DIM / BN), GEMM_THREADS, GEMM_SMEM>>>(out_e, W3);
    softmax_kernel<<<N_DIM, 256>>>(alpha_out, c_out);
    context_kernel<<<dim3(N_DIM, 16), 256>>>(out_e, alpha_out, c_out);
}

// round 7
// speedup vs baseline: 1.1739x; 1.1737x over previous
#include <cuda_runtime.h>
#include <cuda_bf16.h>
#include <math.h>
#include <stdint.h>

#define S_DIM 2048
#define N_DIM 32
#define H_DIM 1024
#define E_DIM 1024
#define M_TOTAL (S_DIM * N_DIM)

// ---------------- GEMM config ----------------
#define BM 128
#define BN 256
#define BK 32
#define NKT (H_DIM / BK)             // 32 k-stages
#define GT 512                        // 16 warps: 4 along M x 4 along N, warp tile 32x64
#define LDS_H 40                      // halves per row: 32 data + 8 pad (80B, 16B-aligned)
#define ROW_B (LDS_H * 2)             // 80 bytes
#define OFF_AH 0
#define OFF_AL (BM * ROW_B)           // 10240
#define OFF_BH (2 * BM * ROW_B)       // 20480
#define OFF_BL (OFF_BH + BN * ROW_B)  // 40960
#define STAGE_BYTES (OFF_BL + BN * ROW_B)  // 61440
#define GEMM_SMEM (3 * STAGE_BYTES + 128)

// ---------------- device scratch ----------------
__device__ __align__(256) __nv_bfloat16 g_Ah[M_TOTAL * H_DIM];   // 128 MB
__device__ __align__(256) __nv_bfloat16 g_Al[M_TOTAL * H_DIM];   // 128 MB
__device__ __align__(256) __nv_bfloat16 g_W2h[E_DIM * H_DIM];    // 2 MB
__device__ __align__(256) __nv_bfloat16 g_W2l[E_DIM * H_DIM];    // 2 MB
__device__ float g_baseT[E_DIM * N_DIM];                          // [e][n]
__device__ float g_a[M_TOTAL];

// ---------------- helpers ----------------
__device__ __forceinline__ void ldmx4(uint32_t* r, uint32_t addr) {
    asm volatile("ldmatrix.sync.aligned.m8n8.x4.shared.b16 {%0,%1,%2,%3}, [%4];"
                 : "=r"(r[0]), "=r"(r[1]), "=r"(r[2]), "=r"(r[3]) : "r"(addr));
}
__device__ __forceinline__ void mma16816(float* c, const uint32_t* a, uint32_t b0, uint32_t b1) {
    asm volatile("mma.sync.aligned.m16n8k16.row.col.f32.bf16.bf16.f32 "
                 "{%0,%1,%2,%3}, {%4,%5,%6,%7}, {%8,%9}, {%0,%1,%2,%3};"
                 : "+f"(c[0]), "+f"(c[1]), "+f"(c[2]), "+f"(c[3])
                 : "r"(a[0]), "r"(a[1]), "r"(a[2]), "r"(a[3]), "r"(b0), "r"(b1));
}
__device__ __forceinline__ void cp16(uint32_t dst, const void* src) {
    asm volatile("cp.async.cg.shared.global [%0], [%1], 16;" :: "r"(dst), "l"(src) : "memory");
}
#define CP_COMMIT() asm volatile("cp.async.commit_group;" ::: "memory")
#define CP_WAIT1()  asm volatile("cp.async.wait_group 1;" ::: "memory")
#define CP_WAIT0()  asm volatile("cp.async.wait_group 0;" ::: "memory")

// ---------------- P0: split A & W2 to bf16 hi/lo, baseT, zero logits ----------------
#define PREP_A 16384
#define PREP_W 256
__device__ __forceinline__ void split4(float4 v, __nv_bfloat162* ph, __nv_bfloat162* pl) {
    __nv_bfloat16 h0 = __float2bfloat16(v.x), h1 = __float2bfloat16(v.y);
    __nv_bfloat16 h2 = __float2bfloat16(v.z), h3 = __float2bfloat16(v.w);
    ph[0] = __halves2bfloat162(h0, h1);
    ph[1] = __halves2bfloat162(h2, h3);
    pl[0] = __halves2bfloat162(__float2bfloat16(v.x - __bfloat162float(h0)),
                               __float2bfloat16(v.y - __bfloat162float(h1)));
    pl[1] = __halves2bfloat162(__float2bfloat16(v.z - __bfloat162float(h2)),
                               __float2bfloat16(v.w - __bfloat162float(h3)));
}
__global__ void prep_kernel(const float4* __restrict__ A4, const float4* __restrict__ W24,
                            const float* __restrict__ hidden, const float* __restrict__ W1,
                            const float* __restrict__ b1, const float* __restrict__ b2) {
    int b = blockIdx.x, t = threadIdx.x;
    if (b < PREP_A) {
        #pragma unroll
        for (int k = 0; k < 4; ++k) {
            int i4 = b * 1024 + k * 256 + t;
            split4(A4[i4], (__nv_bfloat162*)g_Ah + i4 * 2, (__nv_bfloat162*)g_Al + i4 * 2);
        }
    } else if (b < PREP_A + PREP_W) {
        int bb = b - PREP_A;
        #pragma unroll
        for (int k = 0; k < 4; ++k) {
            int i4 = bb * 1024 + k * 256 + t;
            split4(W24[i4], (__nv_bfloat162*)g_W2h + i4 * 2, (__nv_bfloat162*)g_W2l + i4 * 2);
        }
    } else {
        int e = b - (PREP_A + PREP_W);
        int w = t >> 5, ln = t & 31;
        if (t < 64) g_a[e * 64 + t] = 0.0f;
        const float* w1r = W1 + e * H_DIM;
        float bias = b1[e] + b2[e];
        for (int n = w; n < N_DIM; n += 8) {
            const float* hr = hidden + n * H_DIM;
            float acc = 0.0f;
            #pragma unroll 4
            for (int h = ln; h < H_DIM; h += 32) acc += hr[h] * w1r[h];
            #pragma unroll
            for (int o = 16; o; o >>= 1) acc += __shfl_xor_sync(0xffffffffu, acc, o);
            if (ln == 0) g_baseT[e * N_DIM + n] = acc + bias;
        }
    }
}

// ---------------- K1: bf16 mma.sync GEMM + tanh·W3 epilogue -> logits ----------------
__global__ void __launch_bounds__(GT, 1) gemm_kernel(const float* __restrict__ W3) {
    extern __shared__ char smem_raw[];
    uint32_t sraw;
    asm("{ .reg .u64 t; cvta.to.shared.u64 t, %1; cvt.u32.u64 %0, t; }" : "=r"(sraw) : "l"(smem_raw));
    const uint32_t base = (sraw + 127) & ~127u;
    char* smem_al = smem_raw + (base - sraw);

    const int tid = threadIdx.x;
    const int lane = tid & 31;
    const int wid = tid >> 5;
    const int wM = wid & 3;          // 4 x 32 rows
    const int wN = wid >> 2;         // 4 x 64 cols
    const int eBase = blockIdx.x * BN;   // 4 slabs (x fastest -> A shared in L2)
    const int mBase = blockIdx.y * BM;   // 512 m-tiles

    float acc[2][8][4];
    #pragma unroll
    for (int i = 0; i < 2; i++)
        #pragma unroll
        for (int j = 0; j < 8; j++)
            #pragma unroll
            for (int k = 0; k < 4; k++) acc[i][j][k] = 0.0f;

    auto load_stage = [&](int s, int buf) {
        uint32_t sb = base + buf * STAGE_BYTES;
        int k0 = s * BK;
        {   // A: 128 rows x 4 chunks, 1 cp16 per thread per matrix
            int r = tid >> 2, c = tid & 3;
            uint32_t d = r * ROW_B + c * 16;
            size_t go = (size_t)(mBase + r) * H_DIM + k0 + c * 8;
            cp16(sb + OFF_AH + d, g_Ah + go);
            cp16(sb + OFF_AL + d, g_Al + go);
        }
        #pragma unroll
        for (int i = 0; i < 2; i++) {   // B: 256 rows x 4 chunks, 2 cp16 per thread per matrix
            int idx = i * GT + tid, r = idx >> 2, c = idx & 3;
            uint32_t d = r * ROW_B + c * 16;
            size_t go = (size_t)(eBase + r) * H_DIM + k0 + c * 8;
            cp16(sb + OFF_BH + d, g_W2h + go);
            cp16(sb + OFF_BL + d, g_W2l + go);
        }
        CP_COMMIT();
    };

    auto compute = [&](int buf) {
        uint32_t sb = base + buf * STAGE_BYTES;
        uint32_t aH = sb + OFF_AH, aL = sb + OFF_AL, bH = sb + OFF_BH, bL = sb + OFF_BL;
        uint32_t ah[2][2][4], al[2][2][4];
        #pragma unroll
        for (int mt = 0; mt < 2; mt++)
            #pragma unroll
            for (int ks = 0; ks < 2; ks++) {
                int row = wM * 32 + mt * 16 + (lane & 15);
                uint32_t off = row * ROW_B + ks * 32 + ((lane >> 4) * 16);
                ldmx4(ah[mt][ks], aH + off);
                ldmx4(al[mt][ks], aL + off);
            }
        #pragma unroll
        for (int nt = 0; nt < 8; nt++) {
            uint32_t bh[4], bl[4];
            int row = wN * 64 + nt * 8 + (lane & 7);
            uint32_t off = row * ROW_B + ((lane >> 3) * 16);
            ldmx4(bh, bH + off);
            ldmx4(bl, bL + off);
            #pragma unroll
            for (int mt = 0; mt < 2; mt++) {
                mma16816(acc[mt][nt], ah[mt][0], bh[0], bh[1]);
                mma16816(acc[mt][nt], ah[mt][1], bh[2], bh[3]);
                mma16816(acc[mt][nt], ah[mt][0], bl[0], bl[1]);
                mma16816(acc[mt][nt], ah[mt][1], bl[2], bl[3]);
                mma16816(acc[mt][nt], al[mt][0], bh[0], bh[1]);
                mma16816(acc[mt][nt], al[mt][1], bh[2], bh[3]);
            }
        }
    };

    load_stage(0, 0);
    load_stage(1, 1);
    #pragma unroll 1
    for (int kt = 0; kt < NKT; ++kt) {
        if (kt + 1 < NKT) CP_WAIT1(); else CP_WAIT0();
        __syncthreads();                      // stage kt visible; compute(kt-1) done by all
        if (kt + 2 < NKT) load_stage(kt + 2, (kt + 2) % 3);
        compute(kt % 3);
    }
    __syncthreads();

    // ---- epilogue: logits partial over this e-slab ----
    float* sBase = (float*)smem_al;           // [256 e][32 n] = 32 KB
    float* sW3 = sBase + BN * 32;
    for (int idx = tid; idx < BN * 32; idx += GT) sBase[idx] = g_baseT[eBase * 32 + idx];
    if (tid < BN) sW3[tid] = W3[eBase + tid];
    __syncthreads();

    #pragma unroll
    for (int mt = 0; mt < 2; mt++)
        #pragma unroll
        for (int rp = 0; rp < 2; rp++) {
            int rloc = wM * 32 + mt * 16 + rp * 8 + (lane >> 2);
            int n = rloc & 31;
            float part = 0.0f;
            #pragma unroll
            for (int nt = 0; nt < 8; nt++) {
                int el = wN * 64 + nt * 8 + ((lane & 3) << 1);
                float p0 = acc[mt][nt][rp * 2 + 0] + sBase[el * 32 + n];
                float p1 = acc[mt][nt][rp * 2 + 1] + sBase[(el + 1) * 32 + n];
                part += sW3[el] * tanhf(p0) + sW3[el + 1] * tanhf(p1);
            }
            part += __shfl_xor_sync(0xffffffffu, part, 1);
            part += __shfl_xor_sync(0xffffffffu, part, 2);
            if ((lane & 3) == 0) atomicAdd(&g_a[mBase + rloc], part);
        }
}

// ---------------- K2: softmax over S per n; zeroes context region ----------------
__global__ void softmax_kernel(float* __restrict__ alpha, float* __restrict__ c) {
    int n = blockIdx.x, tid = threadIdx.x;
    ((float4*)(c + n * H_DIM))[tid] = make_float4(0.f, 0.f, 0.f, 0.f);
    float v[8], mx = -1e30f;
    #pragma unroll
    for (int i = 0; i < 8; i++) {
        v[i] = g_a[(i * 256 + tid) * N_DIM + n];
        mx = fmaxf(mx, v[i]);
    }
    #pragma unroll
    for (int o = 16; o; o >>= 1) mx = fmaxf(mx, __shfl_xor_sync(0xffffffffu, mx, o));
    __shared__ float sm[8];
    if ((tid & 31) == 0) sm[tid >> 5] = mx;
    __syncthreads();
    float bm = fmaxf(fmaxf(fmaxf(sm[0], sm[1]), fmaxf(sm[2], sm[3])),
                     fmaxf(fmaxf(sm[4], sm[5]), fmaxf(sm[6], sm[7])));
    float sum = 0.0f;
    #pragma unroll
    for (int i = 0; i < 8; i++) { v[i] = expf(v[i] - bm); sum += v[i]; }
    #pragma unroll
    for (int o = 16; o; o >>= 1) sum += __shfl_xor_sync(0xffffffffu, sum, o);
    __syncthreads();
    if ((tid & 31) == 0) sm[tid >> 5] = sum;
    __syncthreads();
    float inv = 1.0f / (sm[0] + sm[1] + sm[2] + sm[3] + sm[4] + sm[5] + sm[6] + sm[7]);
    #pragma unroll
    for (int i = 0; i < 8; i++) alpha[(i * 256 + tid) * N_DIM + n] = v[i] * inv;
}

// ---------------- K3: c[n][h] = sum_s alpha[s,n]*out_e[s,n,h] ----------------
__global__ void context_kernel(const float* __restrict__ out_e,
                               const float* __restrict__ alpha, float* __restrict__ c) {
    int n = blockIdx.x, sc = blockIdx.y, tid = threadIdx.x;
    const float4* p = (const float4*)out_e + (size_t)n * (H_DIM / 4) + tid;
    const size_t srow = (size_t)N_DIM * H_DIM / 4;
    float4 acc = make_float4(0.f, 0.f, 0.f, 0.f);
    int s0 = sc * 128;
    #pragma unroll 4
    for (int s = s0; s < s0 + 128; ++s) {
        float al = alpha[s * N_DIM + n];
        float4 x = p[s * srow];
        acc.x += al * x.x; acc.y += al * x.y; acc.z += al * x.z; acc.w += al * x.w;
    }
    float* dst = c + n * H_DIM + tid * 4;
    atomicAdd(dst + 0, acc.x); atomicAdd(dst + 1, acc.y);
    atomicAdd(dst + 2, acc.z); atomicAdd(dst + 3, acc.w);
}

// ---------------- launch ----------------
extern "C" void kernel_launch(void* const* d_in, const int* in_sizes, int n_in,
                              void* d_out, int out_size) {
    const float* out_e  = (const float*)d_in[0];
    const float* hidden = (const float*)d_in[1];
    const float* W1     = (const float*)d_in[2];
    const float* b1     = (const float*)d_in[3];
    const float* W2     = (const float*)d_in[4];
    const float* b2     = (const float*)d_in[5];
    const float* W3     = (const float*)d_in[6];
    // b3: softmax-invariant, unused.

    float* c_out = (float*)d_out;
    float* alpha_out = c_out + N_DIM * H_DIM;

    static int init = 0;
    if (!init) {
        cudaFuncSetAttribute(gemm_kernel, cudaFuncAttributeMaxDynamicSharedMemorySize, GEMM_SMEM);
        init = 1;
    }

    prep_kernel<<<PREP_A + PREP_W + E_DIM, 256>>>((const float4*)out_e, (const float4*)W2,
                                                  hidden, W1, b1, b2);
    gemm_kernel<<<dim3(E_DIM / BN, M_TOTAL / BM), GT, GEMM_SMEM>>>(W3);
    softmax_kernel<<<N_DIM, 256>>>(alpha_out, c_out);
    context_kernel<<<dim3(N_DIM, 16), 256>>>(out_e, alpha_out, c_out);
}

// round 8
// speedup vs baseline: 1.5590x; 1.3280x over previous
#include <cuda_runtime.h>
#include <cuda_fp16.h>
#include <math.h>
#include <stdint.h>

#define S_DIM 2048
#define N_DIM 32
#define H_DIM 1024
#define E_DIM 1024
#define M_TOTAL (S_DIM * N_DIM)

// ---------------- GEMM config ----------------
#define BM 128
#define BN 256
#define BK 64
#define NKT (H_DIM / BK)              // 16 k-stages
#define GT 512                         // 16 warps: 4 along M x 4 along N, warp tile 32x64
#define ROW_B 144                      // 64 halves (128B) + 16B pad -> conflict-free ldmatrix
#define OFF_AH 0
#define OFF_AL (BM * ROW_B)            // 18432
#define OFF_B  (2 * BM * ROW_B)        // 36864
#define STAGE_BYTES (OFF_B + BN * ROW_B)   // 73728
#define GEMM_SMEM (3 * STAGE_BYTES)    // 221184

// ---------------- device scratch ----------------
__device__ __align__(256) __half g_Ah[M_TOTAL * H_DIM];   // 128 MB
__device__ __align__(256) __half g_Al[M_TOTAL * H_DIM];   // 128 MB
__device__ __align__(256) __half g_W2f[E_DIM * H_DIM];    // 2 MB
__device__ float g_baseT[E_DIM * N_DIM];                   // [e][n]
__device__ float g_a[M_TOTAL];

// ---------------- helpers ----------------
__device__ __forceinline__ void ldmx4(uint32_t* r, uint32_t addr) {
    asm volatile("ldmatrix.sync.aligned.m8n8.x4.shared.b16 {%0,%1,%2,%3}, [%4];"
                 : "=r"(r[0]), "=r"(r[1]), "=r"(r[2]), "=r"(r[3]) : "r"(addr));
}
__device__ __forceinline__ void mma16816(float* c, const uint32_t* a, uint32_t b0, uint32_t b1) {
    asm volatile("mma.sync.aligned.m16n8k16.row.col.f32.f16.f16.f32 "
                 "{%0,%1,%2,%3}, {%4,%5,%6,%7}, {%8,%9}, {%0,%1,%2,%3};"
                 : "+f"(c[0]), "+f"(c[1]), "+f"(c[2]), "+f"(c[3])
                 : "r"(a[0]), "r"(a[1]), "r"(a[2]), "r"(a[3]), "r"(b0), "r"(b1));
}
__device__ __forceinline__ void cp16(uint32_t dst, const void* src) {
    asm volatile("cp.async.cg.shared.global [%0], [%1], 16;" :: "r"(dst), "l"(src) : "memory");
}
#define CP_COMMIT() asm volatile("cp.async.commit_group;" ::: "memory")
#define CP_WAIT1()  asm volatile("cp.async.wait_group 1;" ::: "memory")
#define CP_WAIT0()  asm volatile("cp.async.wait_group 0;" ::: "memory")

// ---------------- P0: split A to fp16 hi/lo, W2 to fp16, baseT, zero logits ----------------
#define PREP_A 16384
#define PREP_W 256
__global__ void prep_kernel(const float4* __restrict__ A4, const float4* __restrict__ W24,
                            const float* __restrict__ hidden, const float* __restrict__ W1,
                            const float* __restrict__ b1, const float* __restrict__ b2) {
    int b = blockIdx.x, t = threadIdx.x;
    if (b < PREP_A) {
        #pragma unroll
        for (int k = 0; k < 4; ++k) {
            int i4 = b * 1024 + k * 256 + t;
            float4 v = A4[i4];
            __half h0 = __float2half(v.x), h1 = __float2half(v.y);
            __half h2 = __float2half(v.z), h3 = __float2half(v.w);
            ((__half2*)g_Ah)[i4 * 2 + 0] = __halves2half2(h0, h1);
            ((__half2*)g_Ah)[i4 * 2 + 1] = __halves2half2(h2, h3);
            ((__half2*)g_Al)[i4 * 2 + 0] = __halves2half2(
                __float2half(v.x - __half2float(h0)), __float2half(v.y - __half2float(h1)));
            ((__half2*)g_Al)[i4 * 2 + 1] = __halves2half2(
                __float2half(v.z - __half2float(h2)), __float2half(v.w - __half2float(h3)));
        }
    } else if (b < PREP_A + PREP_W) {
        int bb = b - PREP_A;
        #pragma unroll
        for (int k = 0; k < 4; ++k) {
            int i4 = bb * 1024 + k * 256 + t;
            float4 v = W24[i4];
            ((__half2*)g_W2f)[i4 * 2 + 0] = __halves2half2(__float2half(v.x), __float2half(v.y));
            ((__half2*)g_W2f)[i4 * 2 + 1] = __halves2half2(__float2half(v.z), __float2half(v.w));
        }
    } else {
        int e = b - (PREP_A + PREP_W);
        int w = t >> 5, ln = t & 31;
        if (t < 64) g_a[e * 64 + t] = 0.0f;
        const float* w1r = W1 + e * H_DIM;
        float bias = b1[e] + b2[e];
        for (int n = w; n < N_DIM; n += 8) {
            const float* hr = hidden + n * H_DIM;
            float acc = 0.0f;
            #pragma unroll 4
            for (int h = ln; h < H_DIM; h += 32) acc += hr[h] * w1r[h];
            #pragma unroll
            for (int o = 16; o; o >>= 1) acc += __shfl_xor_sync(0xffffffffu, acc, o);
            if (ln == 0) g_baseT[e * N_DIM + n] = acc + bias;
        }
    }
}

// ---------------- K1: fp16 2-product mma.sync GEMM + tanh·W3 epilogue ----------------
__global__ void __launch_bounds__(GT, 1) gemm_kernel(const float* __restrict__ W3) {
    extern __shared__ char smem_raw[];
    uint32_t sraw;
    asm("{ .reg .u64 t; cvta.to.shared.u64 t, %1; cvt.u32.u64 %0, t; }" : "=r"(sraw) : "l"(smem_raw));
    const uint32_t base = sraw;        // dynamic smem is 1KB-aligned already (16B enough)
    char* smem_al = smem_raw;

    const int tid = threadIdx.x;
    const int lane = tid & 31;
    const int wid = tid >> 5;
    const int wM = wid & 3;            // 4 x 32 rows
    const int wN = wid >> 2;           // 4 x 64 cols
    const int eBase = blockIdx.x * BN; // x fastest -> 4 CTAs share A tile in L2
    const int mBase = blockIdx.y * BM;

    float acc[2][8][4];
    #pragma unroll
    for (int i = 0; i < 2; i++)
        #pragma unroll
        for (int j = 0; j < 8; j++)
            #pragma unroll
            for (int k = 0; k < 4; k++) acc[i][j][k] = 0.0f;

    auto load_stage = [&](int s, int buf) {
        uint32_t sb = base + buf * STAGE_BYTES;
        int k0 = s * BK;
        #pragma unroll
        for (int i = 0; i < 2; i++) {   // A hi & lo: 128 rows x 8 chunks of 16B
            int idx = i * GT + tid, r = idx >> 3, c = idx & 7;
            uint32_t d = r * ROW_B + c * 16;
            size_t go = (size_t)(mBase + r) * H_DIM + k0 + c * 8;
            cp16(sb + OFF_AH + d, g_Ah + go);
            cp16(sb + OFF_AL + d, g_Al + go);
        }
        #pragma unroll
        for (int i = 0; i < 4; i++) {   // B: 256 rows x 8 chunks
            int idx = i * GT + tid, r = idx >> 3, c = idx & 7;
            uint32_t d = r * ROW_B + c * 16;
            size_t go = (size_t)(eBase + r) * H_DIM + k0 + c * 8;
            cp16(sb + OFF_B + d, g_W2f + go);
        }
        CP_COMMIT();
    };

    auto compute = [&](int buf) {
        uint32_t sb = base + buf * STAGE_BYTES;
        uint32_t aH = sb + OFF_AH, aL = sb + OFF_AL, bB = sb + OFF_B;
        #pragma unroll
        for (int ks2 = 0; ks2 < 2; ks2++) {      // two k32 chunks
            uint32_t ah[2][2][4], al[2][2][4];
            #pragma unroll
            for (int mt = 0; mt < 2; mt++)
                #pragma unroll
                for (int ku = 0; ku < 2; ku++) { // k16 sub-chunks
                    int row = wM * 32 + mt * 16 + (lane & 15);
                    uint32_t off = row * ROW_B + ks2 * 64 + ku * 32 + ((lane >> 4) * 16);
                    ldmx4(ah[mt][ku], aH + off);
                    ldmx4(al[mt][ku], aL + off);
                }
            #pragma unroll
            for (int nt = 0; nt < 8; nt++) {
                uint32_t bf[4];
                int row = wN * 64 + nt * 8 + (lane & 7);
                uint32_t off = row * ROW_B + ks2 * 64 + ((lane >> 3) * 16);
                ldmx4(bf, bB + off);
                #pragma unroll
                for (int mt = 0; mt < 2; mt++) {
                    mma16816(acc[mt][nt], ah[mt][0], bf[0], bf[1]);
                    mma16816(acc[mt][nt], al[mt][0], bf[0], bf[1]);
                    mma16816(acc[mt][nt], ah[mt][1], bf[2], bf[3]);
                    mma16816(acc[mt][nt], al[mt][1], bf[2], bf[3]);
                }
            }
        }
    };

    load_stage(0, 0);
    load_stage(1, 1);
    #pragma unroll 1
    for (int kt = 0; kt < NKT; ++kt) {
        if (kt + 1 < NKT) CP_WAIT1(); else CP_WAIT0();
        __syncthreads();
        if (kt + 2 < NKT) load_stage(kt + 2, (kt + 2) % 3);
        compute(kt % 3);
    }
    __syncthreads();

    // ---- epilogue: logits partial over this e-slab ----
    float* sBase = (float*)smem_al;          // [256 e][32 n] = 32 KB
    float* sW3 = sBase + BN * 32;
    for (int idx = tid; idx < BN * 32; idx += GT) sBase[idx] = g_baseT[eBase * 32 + idx];
    if (tid < BN) sW3[tid] = W3[eBase + tid];
    __syncthreads();

    #pragma unroll
    for (int mt = 0; mt < 2; mt++)
        #pragma unroll
        for (int rp = 0; rp < 2; rp++) {
            int rloc = wM * 32 + mt * 16 + rp * 8 + (lane >> 2);
            int n = rloc & 31;
            float part = 0.0f;
            #pragma unroll
            for (int nt = 0; nt < 8; nt++) {
                int el = wN * 64 + nt * 8 + ((lane & 3) << 1);
                float p0 = acc[mt][nt][rp * 2 + 0] + sBase[el * 32 + n];
                float p1 = acc[mt][nt][rp * 2 + 1] + sBase[(el + 1) * 32 + n];
                part += sW3[el] * tanhf(p0) + sW3[el + 1] * tanhf(p1);
            }
            part += __shfl_xor_sync(0xffffffffu, part, 1);
            part += __shfl_xor_sync(0xffffffffu, part, 2);
            if ((lane & 3) == 0) atomicAdd(&g_a[mBase + rloc], part);
        }
}

// ---------------- K2: softmax over S per n; zeroes context region ----------------
__global__ void softmax_kernel(float* __restrict__ alpha, float* __restrict__ c) {
    int n = blockIdx.x, tid = threadIdx.x;
    ((float4*)(c + n * H_DIM))[tid] = make_float4(0.f, 0.f, 0.f, 0.f);
    float v[8], mx = -1e30f;
    #pragma unroll
    for (int i = 0; i < 8; i++) {
        v[i] = g_a[(i * 256 + tid) * N_DIM + n];
        mx = fmaxf(mx, v[i]);
    }
    #pragma unroll
    for (int o = 16; o; o >>= 1) mx = fmaxf(mx, __shfl_xor_sync(0xffffffffu, mx, o));
    __shared__ float sm[8];
    if ((tid & 31) == 0) sm[tid >> 5] = mx;
    __syncthreads();
    float bm = fmaxf(fmaxf(fmaxf(sm[0], sm[1]), fmaxf(sm[2], sm[3])),
                     fmaxf(fmaxf(sm[4], sm[5]), fmaxf(sm[6], sm[7])));
    float sum = 0.0f;
    #pragma unroll
    for (int i = 0; i < 8; i++) { v[i] = expf(v[i] - bm); sum += v[i]; }
    #pragma unroll
    for (int o = 16; o; o >>= 1) sum += __shfl_xor_sync(0xffffffffu, sum, o);
    __syncthreads();
    if ((tid & 31) == 0) sm[tid >> 5] = sum;
    __syncthreads();
    float inv = 1.0f / (sm[0] + sm[1] + sm[2] + sm[3] + sm[4] + sm[5] + sm[6] + sm[7]);
    #pragma unroll
    for (int i = 0; i < 8; i++) alpha[(i * 256 + tid) * N_DIM + n] = v[i] * inv;
}

// ---------------- K3: c[n][h] = sum_s alpha[s,n]*out_e[s,n,h] ----------------
__global__ void context_kernel(const float* __restrict__ out_e,
                               const float* __restrict__ alpha, float* __restrict__ c) {
    int n = blockIdx.x, sc = blockIdx.y, tid = threadIdx.x;
    const float4* p = (const float4*)out_e + (size_t)n * (H_DIM / 4) + tid;
    const size_t srow = (size_t)N_DIM * H_DIM / 4;
    float4 acc = make_float4(0.f, 0.f, 0.f, 0.f);
    int s0 = sc * 128;
    #pragma unroll 4
    for (int s = s0; s < s0 + 128; ++s) {
        float al = alpha[s * N_DIM + n];
        float4 x = p[s * srow];
        acc.x += al * x.x; acc.y += al * x.y; acc.z += al * x.z; acc.w += al * x.w;
    }
    float* dst = c + n * H_DIM + tid * 4;
    atomicAdd(dst + 0, acc.x); atomicAdd(dst + 1, acc.y);
    atomicAdd(dst + 2, acc.z); atomicAdd(dst + 3, acc.w);
}

// ---------------- launch ----------------
extern "C" void kernel_launch(void* const* d_in, const int* in_sizes, int n_in,
                              void* d_out, int out_size) {
    const float* out_e  = (const float*)d_in[0];
    const float* hidden = (const float*)d_in[1];
    const float* W1     = (const float*)d_in[2];
    const float* b1     = (const float*)d_in[3];
    const float* W2     = (const float*)d_in[4];
    const float* b2     = (const float*)d_in[5];
    const float* W3     = (const float*)d_in[6];
    // b3: softmax-invariant, unused.

    float* c_out = (float*)d_out;
    float* alpha_out = c_out + N_DIM * H_DIM;

    static int init = 0;
    if (!init) {
        cudaFuncSetAttribute(gemm_kernel, cudaFuncAttributeMaxDynamicSharedMemorySize, GEMM_SMEM);
        init = 1;
    }

    prep_kernel<<<PREP_A + PREP_W + E_DIM, 256>>>((const float4*)out_e, (const float4*)W2,
                                                  hidden, W1, b1, b2);
    gemm_kernel<<<dim3(E_DIM / BN, M_TOTAL / BM), GT, GEMM_SMEM>>>(W3);
    softmax_kernel<<<N_DIM, 256>>>(alpha_out, c_out);
    context_kernel<<<dim3(N_DIM, 16), 256>>>(out_e, alpha_out, c_out);
}

// round 9
// speedup vs baseline: 2.4834x; 1.5929x over previous
#include <cuda_runtime.h>
#include <cuda_fp16.h>
#include <math.h>
#include <stdint.h>

#define S_DIM 2048
#define N_DIM 32
#define H_DIM 1024
#define E_DIM 1024
#define M_TOTAL (S_DIM * N_DIM)

// ---------------- GEMM config ----------------
#define BM 128
#define BN 256
#define BK 64
#define NKT (H_DIM / BK)              // 16 k-stages
#define GT 512                         // 16 warps: 4 along M x 4 along N, warp tile 32x64
#define ROW_B 144                      // 64 halves (128B) + 16B pad -> conflict-free ldmatrix
#define OFF_A 0
#define OFF_B (BM * ROW_B)             // 18432
#define STAGE_BYTES (OFF_B + BN * ROW_B)   // 55296
#define GEMM_SMEM (3 * STAGE_BYTES)    // 165888

// ---------------- device scratch ----------------
__device__ __align__(256) __half g_Af[M_TOTAL * H_DIM];   // 128 MB (A as fp16)
__device__ __align__(256) __half g_W2f[E_DIM * H_DIM];    // 2 MB
__device__ float g_baseT[E_DIM * N_DIM];                   // [e][n]
__device__ float g_a[M_TOTAL];

// ---------------- helpers ----------------
__device__ __forceinline__ void ldmx4(uint32_t* r, uint32_t addr) {
    asm volatile("ldmatrix.sync.aligned.m8n8.x4.shared.b16 {%0,%1,%2,%3}, [%4];"
                 : "=r"(r[0]), "=r"(r[1]), "=r"(r[2]), "=r"(r[3]) : "r"(addr));
}
__device__ __forceinline__ void mma16816(float* c, const uint32_t* a, uint32_t b0, uint32_t b1) {
    asm volatile("mma.sync.aligned.m16n8k16.row.col.f32.f16.f16.f32 "
                 "{%0,%1,%2,%3}, {%4,%5,%6,%7}, {%8,%9}, {%0,%1,%2,%3};"
                 : "+f"(c[0]), "+f"(c[1]), "+f"(c[2]), "+f"(c[3])
                 : "r"(a[0]), "r"(a[1]), "r"(a[2]), "r"(a[3]), "r"(b0), "r"(b1));
}
__device__ __forceinline__ void cp16(uint32_t dst, const void* src) {
    asm volatile("cp.async.cg.shared.global [%0], [%1], 16;" :: "r"(dst), "l"(src) : "memory");
}
#define CP_COMMIT() asm volatile("cp.async.commit_group;" ::: "memory")
#define CP_WAIT1()  asm volatile("cp.async.wait_group 1;" ::: "memory")
#define CP_WAIT0()  asm volatile("cp.async.wait_group 0;" ::: "memory")

// ---------------- P0: A->fp16, W2->fp16, baseT, zero logits ----------------
#define PREP_A 16384
#define PREP_W 256
__global__ void prep_kernel(const float4* __restrict__ A4, const float4* __restrict__ W24,
                            const float* __restrict__ hidden, const float* __restrict__ W1,
                            const float* __restrict__ b1, const float* __restrict__ b2) {
    int b = blockIdx.x, t = threadIdx.x;
    if (b < PREP_A) {
        #pragma unroll
        for (int k = 0; k < 4; ++k) {
            int i4 = b * 1024 + k * 256 + t;
            float4 v = A4[i4];
            ((__half2*)g_Af)[i4 * 2 + 0] = __halves2half2(__float2half(v.x), __float2half(v.y));
            ((__half2*)g_Af)[i4 * 2 + 1] = __halves2half2(__float2half(v.z), __float2half(v.w));
        }
    } else if (b < PREP_A + PREP_W) {
        int bb = b - PREP_A;
        #pragma unroll
        for (int k = 0; k < 4; ++k) {
            int i4 = bb * 1024 + k * 256 + t;
            float4 v = W24[i4];
            ((__half2*)g_W2f)[i4 * 2 + 0] = __halves2half2(__float2half(v.x), __float2half(v.y));
            ((__half2*)g_W2f)[i4 * 2 + 1] = __halves2half2(__float2half(v.z), __float2half(v.w));
        }
    } else {
        int e = b - (PREP_A + PREP_W);
        int w = t >> 5, ln = t & 31;
        if (t < 64) g_a[e * 64 + t] = 0.0f;
        const float* w1r = W1 + e * H_DIM;
        float bias = b1[e] + b2[e];
        for (int n = w; n < N_DIM; n += 8) {
            const float* hr = hidden + n * H_DIM;
            float acc = 0.0f;
            #pragma unroll 4
            for (int h = ln; h < H_DIM; h += 32) acc += hr[h] * w1r[h];
            #pragma unroll
            for (int o = 16; o; o >>= 1) acc += __shfl_xor_sync(0xffffffffu, acc, o);
            if (ln == 0) g_baseT[e * N_DIM + n] = acc + bias;
        }
    }
}

// ---------------- K1: fp16 mma.sync GEMM + tanh·W3 epilogue -> logits ----------------
__global__ void __launch_bounds__(GT, 1) gemm_kernel(const float* __restrict__ W3) {
    extern __shared__ char smem_raw[];
    uint32_t base;
    asm("{ .reg .u64 t; cvta.to.shared.u64 t, %1; cvt.u32.u64 %0, t; }" : "=r"(base) : "l"(smem_raw));
    char* smem_al = smem_raw;

    const int tid = threadIdx.x;
    const int lane = tid & 31;
    const int wid = tid >> 5;
    const int wM = wid & 3;            // 4 x 32 rows
    const int wN = wid >> 2;           // 4 x 64 cols
    const int eBase = blockIdx.x * BN; // x fastest -> 4 CTAs share A tile in L2
    const int mBase = blockIdx.y * BM;

    float acc[2][8][4];
    #pragma unroll
    for (int i = 0; i < 2; i++)
        #pragma unroll
        for (int j = 0; j < 8; j++)
            #pragma unroll
            for (int k = 0; k < 4; k++) acc[i][j][k] = 0.0f;

    auto load_stage = [&](int s, int buf) {
        uint32_t sb = base + buf * STAGE_BYTES;
        int k0 = s * BK;
        #pragma unroll
        for (int i = 0; i < 2; i++) {   // A: 128 rows x 8 chunks of 16B
            int idx = i * GT + tid, r = idx >> 3, c = idx & 7;
            cp16(sb + OFF_A + r * ROW_B + c * 16,
                 g_Af + (size_t)(mBase + r) * H_DIM + k0 + c * 8);
        }
        #pragma unroll
        for (int i = 0; i < 4; i++) {   // B: 256 rows x 8 chunks
            int idx = i * GT + tid, r = idx >> 3, c = idx & 7;
            cp16(sb + OFF_B + r * ROW_B + c * 16,
                 g_W2f + (size_t)(eBase + r) * H_DIM + k0 + c * 8);
        }
        CP_COMMIT();
    };

    auto compute = [&](int buf) {
        uint32_t sb = base + buf * STAGE_BYTES;
        uint32_t aA = sb + OFF_A, bB = sb + OFF_B;
        #pragma unroll
        for (int ks2 = 0; ks2 < 2; ks2++) {      // two k32 chunks
            uint32_t af[2][2][4];
            #pragma unroll
            for (int mt = 0; mt < 2; mt++)
                #pragma unroll
                for (int ku = 0; ku < 2; ku++) {
                    int row = wM * 32 + mt * 16 + (lane & 15);
                    uint32_t off = row * ROW_B + ks2 * 64 + ku * 32 + ((lane >> 4) * 16);
                    ldmx4(af[mt][ku], aA + off);
                }
            #pragma unroll
            for (int nt = 0; nt < 8; nt++) {
                uint32_t bf[4];
                int row = wN * 64 + nt * 8 + (lane & 7);
                uint32_t off = row * ROW_B + ks2 * 64 + ((lane >> 3) * 16);
                ldmx4(bf, bB + off);
                #pragma unroll
                for (int mt = 0; mt < 2; mt++) {
                    mma16816(acc[mt][nt], af[mt][0], bf[0], bf[1]);
                    mma16816(acc[mt][nt], af[mt][1], bf[2], bf[3]);
                }
            }
        }
    };

    load_stage(0, 0);
    load_stage(1, 1);
    #pragma unroll 1
    for (int kt = 0; kt < NKT; ++kt) {
        if (kt + 1 < NKT) CP_WAIT1(); else CP_WAIT0();
        __syncthreads();
        if (kt + 2 < NKT) load_stage(kt + 2, (kt + 2) % 3);
        compute(kt % 3);
    }
    __syncthreads();

    // ---- epilogue: logits partial over this e-slab ----
    float* sBase = (float*)smem_al;          // [256 e][32 n] = 32 KB
    float* sW3 = sBase + BN * 32;
    for (int idx = tid; idx < BN * 32; idx += GT) sBase[idx] = g_baseT[eBase * 32 + idx];
    if (tid < BN) sW3[tid] = W3[eBase + tid];
    __syncthreads();

    #pragma unroll
    for (int mt = 0; mt < 2; mt++)
        #pragma unroll
        for (int rp = 0; rp < 2; rp++) {
            int rloc = wM * 32 + mt * 16 + rp * 8 + (lane >> 2);
            int n = rloc & 31;
            float part = 0.0f;
            #pragma unroll
            for (int nt = 0; nt < 8; nt++) {
                int el = wN * 64 + nt * 8 + ((lane & 3) << 1);
                float p0 = acc[mt][nt][rp * 2 + 0] + sBase[el * 32 + n];
                float p1 = acc[mt][nt][rp * 2 + 1] + sBase[(el + 1) * 32 + n];
                part += sW3[el] * tanhf(p0) + sW3[el + 1] * tanhf(p1);
            }
            part += __shfl_xor_sync(0xffffffffu, part, 1);
            part += __shfl_xor_sync(0xffffffffu, part, 2);
            if ((lane & 3) == 0) atomicAdd(&g_a[mBase + rloc], part);
        }
}

// ---------------- K2: softmax over S per n; zeroes context region ----------------
__global__ void softmax_kernel(float* __restrict__ alpha, float* __restrict__ c) {
    int n = blockIdx.x, tid = threadIdx.x;
    ((float4*)(c + n * H_DIM))[tid] = make_float4(0.f, 0.f, 0.f, 0.f);
    float v[8], mx = -1e30f;
    #pragma unroll
    for (int i = 0; i < 8; i++) {
        v[i] = g_a[(i * 256 + tid) * N_DIM + n];
        mx = fmaxf(mx, v[i]);
    }
    #pragma unroll
    for (int o = 16; o; o >>= 1) mx = fmaxf(mx, __shfl_xor_sync(0xffffffffu, mx, o));
    __shared__ float sm[8];
    if ((tid & 31) == 0) sm[tid >> 5] = mx;
    __syncthreads();
    float bm = fmaxf(fmaxf(fmaxf(sm[0], sm[1]), fmaxf(sm[2], sm[3])),
                     fmaxf(fmaxf(sm[4], sm[5]), fmaxf(sm[6], sm[7])));
    float sum = 0.0f;
    #pragma unroll
    for (int i = 0; i < 8; i++) { v[i] = expf(v[i] - bm); sum += v[i]; }
    #pragma unroll
    for (int o = 16; o; o >>= 1) sum += __shfl_xor_sync(0xffffffffu, sum, o);
    __syncthreads();
    if ((tid & 31) == 0) sm[tid >> 5] = sum;
    __syncthreads();
    float inv = 1.0f / (sm[0] + sm[1] + sm[2] + sm[3] + sm[4] + sm[5] + sm[6] + sm[7]);
    #pragma unroll
    for (int i = 0; i < 8; i++) alpha[(i * 256 + tid) * N_DIM + n] = v[i] * inv;
}

// ---------------- K3: c[n][h] = sum_s alpha[s,n]*out_e[s,n,h] ----------------
__global__ void context_kernel(const float* __restrict__ out_e,
                               const float* __restrict__ alpha, float* __restrict__ c) {
    int n = blockIdx.x, sc = blockIdx.y, tid = threadIdx.x;
    const float4* p = (const float4*)out_e + (size_t)n * (H_DIM / 4) + tid;
    const size_t srow = (size_t)N_DIM * H_DIM / 4;
    float4 acc = make_float4(0.f, 0.f, 0.f, 0.f);
    int s0 = sc * 128;
    #pragma unroll 4
    for (int s = s0; s < s0 + 128; ++s) {
        float al = alpha[s * N_DIM + n];
        float4 x = p[s * srow];
        acc.x += al * x.x; acc.y += al * x.y; acc.z += al * x.z; acc.w += al * x.w;
    }
    float* dst = c + n * H_DIM + tid * 4;
    atomicAdd(dst + 0, acc.x); atomicAdd(dst + 1, acc.y);
    atomicAdd(dst + 2, acc.z); atomicAdd(dst + 3, acc.w);
}

// ---------------- launch ----------------
extern "C" void kernel_launch(void* const* d_in, const int* in_sizes, int n_in,
                              void* d_out, int out_size) {
    const float* out_e  = (const float*)d_in[0];
    const float* hidden = (const float*)d_in[1];
    const float* W1     = (const float*)d_in[2];
    const float* b1     = (const float*)d_in[3];
    const float* W2     = (const float*)d_in[4];
    const float* b2     = (const float*)d_in[5];
    const float* W3     = (const float*)d_in[6];
    // b3: softmax-invariant, unused.

    float* c_out = (float*)d_out;
    float* alpha_out = c_out + N_DIM * H_DIM;

    static int init = 0;
    if (!init) {
        cudaFuncSetAttribute(gemm_kernel, cudaFuncAttributeMaxDynamicSharedMemorySize, GEMM_SMEM);
        init = 1;
    }

    prep_kernel<<<PREP_A + PREP_W + E_DIM, 256>>>((const float4*)out_e, (const float4*)W2,
                                                  hidden, W1, b1, b2);
    gemm_kernel<<<dim3(E_DIM / BN, M_TOTAL / BM), GT, GEMM_SMEM>>>(W3);
    softmax_kernel<<<N_DIM, 256>>>(alpha_out, c_out);
    context_kernel<<<dim3(N_DIM, 16), 256>>>(out_e, alpha_out, c_out);
}

// round 12
// speedup vs baseline: 2.6108x; 1.0513x over previous
#include <cuda_runtime.h>
#include <cuda_fp16.h>
#include <math.h>
#include <stdint.h>

#define S_DIM 2048
#define N_DIM 32
#define H_DIM 1024
#define E_DIM 1024
#define M_TOTAL (S_DIM * N_DIM)

// ---------------- GEMM config ----------------
#define BM 128
#define BN 256
#define BK 64
#define NKT (H_DIM / BK)              // 16 k-stages
#define GT 256                         // 8 warps: 2 along M x 4 along N, warp tile 64x64
#define ROW_B 144                      // 64 halves (128B) + 16B pad -> conflict-free ldmatrix
#define OFF_A 0
#define OFF_B (BM * ROW_B)             // 18432
#define STAGE_BYTES (OFF_B + BN * ROW_B)   // 55296
#define GEMM_SMEM (3 * STAGE_BYTES)    // 165888

// ---------------- device scratch ----------------
__device__ __align__(256) __half g_Af[M_TOTAL * H_DIM];   // 128 MB (A as fp16)
__device__ __align__(256) __half g_W2f[E_DIM * H_DIM];    // 2 MB
__device__ float g_baseT[E_DIM * N_DIM];                   // [e][n]
__device__ float g_a[M_TOTAL];

// ---------------- helpers ----------------
__device__ __forceinline__ void ldmx4(uint32_t* r, uint32_t addr) {
    asm volatile("ldmatrix.sync.aligned.m8n8.x4.shared.b16 {%0,%1,%2,%3}, [%4];"
                 : "=r"(r[0]), "=r"(r[1]), "=r"(r[2]), "=r"(r[3]) : "r"(addr));
}
__device__ __forceinline__ void mma16816(float* c, const uint32_t* a, uint32_t b0, uint32_t b1) {
    asm volatile("mma.sync.aligned.m16n8k16.row.col.f32.f16.f16.f32 "
                 "{%0,%1,%2,%3}, {%4,%5,%6,%7}, {%8,%9}, {%0,%1,%2,%3};"
                 : "+f"(c[0]), "+f"(c[1]), "+f"(c[2]), "+f"(c[3])
                 : "r"(a[0]), "r"(a[1]), "r"(a[2]), "r"(a[3]), "r"(b0), "r"(b1));
}
__device__ __forceinline__ void cp16(uint32_t dst, const void* src) {
    asm volatile("cp.async.cg.shared.global [%0], [%1], 16;" :: "r"(dst), "l"(src) : "memory");
}
#define CP_COMMIT() asm volatile("cp.async.commit_group;" ::: "memory")
#define CP_WAIT1()  asm volatile("cp.async.wait_group 1;" ::: "memory")
#define CP_WAIT0()  asm volatile("cp.async.wait_group 0;" ::: "memory")

// ---------------- P0: A->fp16, W2->fp16, baseT, zero logits ----------------
#define PREP_A 16384
#define PREP_W 256
__global__ void prep_kernel(const float4* __restrict__ A4, const float4* __restrict__ W24,
                            const float* __restrict__ hidden, const float* __restrict__ W1,
                            const float* __restrict__ b1, const float* __restrict__ b2) {
    int b = blockIdx.x, t = threadIdx.x;
    if (b < PREP_A) {
        #pragma unroll
        for (int k = 0; k < 4; ++k) {
            int i4 = b * 1024 + k * 256 + t;
            float4 v = A4[i4];
            ((__half2*)g_Af)[i4 * 2 + 0] = __halves2half2(__float2half(v.x), __float2half(v.y));
            ((__half2*)g_Af)[i4 * 2 + 1] = __halves2half2(__float2half(v.z), __float2half(v.w));
        }
    } else if (b < PREP_A + PREP_W) {
        int bb = b - PREP_A;
        #pragma unroll
        for (int k = 0; k < 4; ++k) {
            int i4 = bb * 1024 + k * 256 + t;
            float4 v = W24[i4];
            ((__half2*)g_W2f)[i4 * 2 + 0] = __halves2half2(__float2half(v.x), __float2half(v.y));
            ((__half2*)g_W2f)[i4 * 2 + 1] = __halves2half2(__float2half(v.z), __float2half(v.w));
        }
    } else {
        int e = b - (PREP_A + PREP_W);
        int w = t >> 5, ln = t & 31;
        if (t < 64) g_a[e * 64 + t] = 0.0f;
        const float* w1r = W1 + e * H_DIM;
        float bias = b1[e] + b2[e];
        for (int n = w; n < N_DIM; n += 8) {
            const float* hr = hidden + n * H_DIM;
            float acc = 0.0f;
            #pragma unroll 4
            for (int h = ln; h < H_DIM; h += 32) acc += hr[h] * w1r[h];
            #pragma unroll
            for (int o = 16; o; o >>= 1) acc += __shfl_xor_sync(0xffffffffu, acc, o);
            if (ln == 0) g_baseT[e * N_DIM + n] = acc + bias;
        }
    }
}

// ---------------- K1: fp16 mma.sync GEMM (64x64 warp tiles) + tanh·W3 epilogue ----------------
__global__ void __launch_bounds__(GT, 1) gemm_kernel(const float* __restrict__ W3) {
    extern __shared__ char smem_raw[];
    uint32_t base;
    asm("{ .reg .u64 t; cvta.to.shared.u64 t, %1; cvt.u32.u64 %0, t; }" : "=r"(base) : "l"(smem_raw));
    char* smem_al = smem_raw;

    const int tid = threadIdx.x;
    const int lane = tid & 31;
    const int wid = tid >> 5;
    const int wM = wid & 1;            // 2 x 64 rows
    const int wN = wid >> 1;           // 4 x 64 cols
    const int eBase = blockIdx.x * BN; // x fastest -> 4 CTAs share A tile in L2
    const int mBase = blockIdx.y * BM;

    float acc[4][8][4];
    #pragma unroll
    for (int i = 0; i < 4; i++)
        #pragma unroll
        for (int j = 0; j < 8; j++)
            #pragma unroll
            for (int k = 0; k < 4; k++) acc[i][j][k] = 0.0f;

    auto load_stage = [&](int s, int buf) {
        uint32_t sb = base + buf * STAGE_BYTES;
        int k0 = s * BK;
        #pragma unroll
        for (int i = 0; i < 4; i++) {   // A: 128 rows x 8 chunks of 16B
            int idx = i * GT + tid, r = idx >> 3, c = idx & 7;
            cp16(sb + OFF_A + r * ROW_B + c * 16,
                 g_Af + (size_t)(mBase + r) * H_DIM + k0 + c * 8);
        }
        #pragma unroll
        for (int i = 0; i < 8; i++) {   // B: 256 rows x 8 chunks
            int idx = i * GT + tid, r = idx >> 3, c = idx & 7;
            cp16(sb + OFF_B + r * ROW_B + c * 16,
                 g_W2f + (size_t)(eBase + r) * H_DIM + k0 + c * 8);
        }
        CP_COMMIT();
    };

    auto compute = [&](int buf) {
        uint32_t sb = base + buf * STAGE_BYTES;
        uint32_t aA = sb + OFF_A, bB = sb + OFF_B;
        #pragma unroll
        for (int ks2 = 0; ks2 < 2; ks2++) {      // two k32 chunks
            uint32_t af[4][2][4];
            #pragma unroll
            for (int mt = 0; mt < 4; mt++)
                #pragma unroll
                for (int ku = 0; ku < 2; ku++) {
                    int row = wM * 64 + mt * 16 + (lane & 15);
                    uint32_t off = row * ROW_B + ks2 * 64 + ku * 32 + ((lane >> 4) * 16);
                    ldmx4(af[mt][ku], aA + off);
                }
            #pragma unroll
            for (int nt = 0; nt < 8; nt++) {
                uint32_t bf[4];
                int row = wN * 64 + nt * 8 + (lane & 7);
                uint32_t off = row * ROW_B + ks2 * 64 + ((lane >> 3) * 16);
                ldmx4(bf, bB + off);
                #pragma unroll
                for (int mt = 0; mt < 4; mt++) {
                    mma16816(acc[mt][nt], af[mt][0], bf[0], bf[1]);
                    mma16816(acc[mt][nt], af[mt][1], bf[2], bf[3]);
                }
            }
        }
    };

    load_stage(0, 0);
    load_stage(1, 1);
    #pragma unroll 1
    for (int kt = 0; kt < NKT; ++kt) {
        if (kt + 1 < NKT) CP_WAIT1(); else CP_WAIT0();
        __syncthreads();
        if (kt + 2 < NKT) load_stage(kt + 2, (kt + 2) % 3);
        compute(kt % 3);
    }
    __syncthreads();

    // ---- epilogue: logits partial over this e-slab ----
    float* sBase = (float*)smem_al;          // [256 e][32 n] = 32 KB
    float* sW3 = sBase + BN * 32;
    for (int idx = tid; idx < BN * 32; idx += GT) sBase[idx] = g_baseT[eBase * 32 + idx];
    if (tid < BN) sW3[tid] = W3[eBase + tid];
    __syncthreads();

    #pragma unroll
    for (int mt = 0; mt < 4; mt++)
        #pragma unroll
        for (int rp = 0; rp < 2; rp++) {
            int rloc = wM * 64 + mt * 16 + rp * 8 + (lane >> 2);
            int n = rloc & 31;
            float part = 0.0f;
            #pragma unroll
            for (int nt = 0; nt < 8; nt++) {
                int el = wN * 64 + nt * 8 + ((lane & 3) << 1);
                float p0 = acc[mt][nt][rp * 2 + 0] + sBase[el * 32 + n];
                float p1 = acc[mt][nt][rp * 2 + 1] + sBase[(el + 1) * 32 + n];
                part += sW3[el] * tanhf(p0) + sW3[el + 1] * tanhf(p1);
            }
            part += __shfl_xor_sync(0xffffffffu, part, 1);
            part += __shfl_xor_sync(0xffffffffu, part, 2);
            if ((lane & 3) == 0) atomicAdd(&g_a[mBase + rloc], part);
        }
}

// ---------------- K2: softmax over S per n; zeroes context region ----------------
__global__ void softmax_kernel(float* __restrict__ alpha, float* __restrict__ c) {
    int n = blockIdx.x, tid = threadIdx.x;
    ((float4*)(c + n * H_DIM))[tid] = make_float4(0.f, 0.f, 0.f, 0.f);
    float v[8], mx = -1e30f;
    #pragma unroll
    for (int i = 0; i < 8; i++) {
        v[i] = g_a[(i * 256 + tid) * N_DIM + n];
        mx = fmaxf(mx, v[i]);
    }
    #pragma unroll
    for (int o = 16; o; o >>= 1) mx = fmaxf(mx, __shfl_xor_sync(0xffffffffu, mx, o));
    __shared__ float sm[8];
    if ((tid & 31) == 0) sm[tid >> 5] = mx;
    __syncthreads();
    float bm = fmaxf(fmaxf(fmaxf(sm[0], sm[1]), fmaxf(sm[2], sm[3])),
                     fmaxf(fmaxf(sm[4], sm[5]), fmaxf(sm[6], sm[7])));
    float sum = 0.0f;
    #pragma unroll
    for (int i = 0; i < 8; i++) { v[i] = expf(v[i] - bm); sum += v[i]; }
    #pragma unroll
    for (int o = 16; o; o >>= 1) sum += __shfl_xor_sync(0xffffffffu, sum, o);
    __syncthreads();
    if ((tid & 31) == 0) sm[tid >> 5] = sum;
    __syncthreads();
    float inv = 1.0f / (sm[0] + sm[1] + sm[2] + sm[3] + sm[4] + sm[5] + sm[6] + sm[7]);
    #pragma unroll
    for (int i = 0; i < 8; i++) alpha[(i * 256 + tid) * N_DIM + n] = v[i] * inv;
}

// ---------------- K3: c[n][h] = sum_s alpha[s,n]*out_e[s,n,h] ----------------
__global__ void context_kernel(const float* __restrict__ out_e,
                               const float* __restrict__ alpha, float* __restrict__ c) {
    int n = blockIdx.x, sc = blockIdx.y, tid = threadIdx.x;
    const float4* p = (const float4*)out_e + (size_t)n * (H_DIM / 4) + tid;
    const size_t srow = (size_t)N_DIM * H_DIM / 4;
    float4 acc = make_float4(0.f, 0.f, 0.f, 0.f);
    int s0 = sc * 128;
    #pragma unroll 4
    for (int s = s0; s < s0 + 128; ++s) {
        float al = alpha[s * N_DIM + n];
        float4 x = p[s * srow];
        acc.x += al * x.x; acc.y += al * x.y; acc.z += al * x.z; acc.w += al * x.w;
    }
    float* dst = c + n * H_DIM + tid * 4;
    atomicAdd(dst + 0, acc.x); atomicAdd(dst + 1, acc.y);
    atomicAdd(dst + 2, acc.z); atomicAdd(dst + 3, acc.w);
}

// ---------------- launch ----------------
extern "C" void kernel_launch(void* const* d_in, const int* in_sizes, int n_in,
                              void* d_out, int out_size) {
    const float* out_e  = (const float*)d_in[0];
    const float* hidden = (const float*)d_in[1];
    const float* W1     = (const float*)d_in[2];
    const float* b1     = (const float*)d_in[3];
    const float* W2     = (const float*)d_in[4];
    const float* b2     = (const float*)d_in[5];
    const float* W3     = (const float*)d_in[6];
    // b3: softmax-invariant, unused.

    float* c_out = (float*)d_out;
    float* alpha_out = c_out + N_DIM * H_DIM;

    static int init = 0;
    if (!init) {
        cudaFuncSetAttribute(gemm_kernel, cudaFuncAttributeMaxDynamicSharedMemorySize, GEMM_SMEM);
        init = 1;
    }

    prep_kernel<<<PREP_A + PREP_W + E_DIM, 256>>>((const float4*)out_e, (const float4*)W2,
                                                  hidden, W1, b1, b2);
    gemm_kernel<<<dim3(E_DIM / BN, M_TOTAL / BM), GT, GEMM_SMEM>>>(W3);
    softmax_kernel<<<N_DIM, 256>>>(alpha_out, c_out);
    context_kernel<<<dim3(N_DIM, 16), 256>>>(out_e, alpha_out, c_out);
}

// round 13
// speedup vs baseline: 2.8660x; 1.0978x over previous
#include <cuda_runtime.h>
#include <cuda_fp16.h>
#include <math.h>
#include <stdint.h>

#define S_DIM 2048
#define N_DIM 32
#define H_DIM 1024
#define E_DIM 1024
#define M_TOTAL (S_DIM * N_DIM)

// ---------------- GEMM config ----------------
#define BM 128
#define BN 128
#define BK 64
#define NKT (H_DIM / BK)              // 16 k-stages
#define GT 256                         // 8 warps: 2 along M x 4 along N, warp tile 64x32
#define ROW_B 144                      // 64 halves (128B) + 16B pad -> conflict-free ldmatrix
#define OFF_A 0
#define OFF_B (BM * ROW_B)             // 18432
#define STAGE_BYTES (OFF_B + BN * ROW_B)   // 36864
#define GEMM_SMEM (3 * STAGE_BYTES)    // 110592 -> 2 CTAs/SM

// ---------------- device scratch ----------------
__device__ __align__(256) __half g_Af[M_TOTAL * H_DIM];   // 128 MB (A as fp16)
__device__ __align__(256) __half g_W2f[E_DIM * H_DIM];    // 2 MB
__device__ float g_baseT[E_DIM * N_DIM];                   // [e][n]
__device__ float g_a[M_TOTAL];

// ---------------- helpers ----------------
__device__ __forceinline__ void ldmx4(uint32_t* r, uint32_t addr) {
    asm volatile("ldmatrix.sync.aligned.m8n8.x4.shared.b16 {%0,%1,%2,%3}, [%4];"
                 : "=r"(r[0]), "=r"(r[1]), "=r"(r[2]), "=r"(r[3]) : "r"(addr));
}
__device__ __forceinline__ void mma16816(float* c, const uint32_t* a, uint32_t b0, uint32_t b1) {
    asm volatile("mma.sync.aligned.m16n8k16.row.col.f32.f16.f16.f32 "
                 "{%0,%1,%2,%3}, {%4,%5,%6,%7}, {%8,%9}, {%0,%1,%2,%3};"
                 : "+f"(c[0]), "+f"(c[1]), "+f"(c[2]), "+f"(c[3])
                 : "r"(a[0]), "r"(a[1]), "r"(a[2]), "r"(a[3]), "r"(b0), "r"(b1));
}
__device__ __forceinline__ void cp16(uint32_t dst, const void* src) {
    asm volatile("cp.async.cg.shared.global [%0], [%1], 16;" :: "r"(dst), "l"(src) : "memory");
}
#define CP_COMMIT() asm volatile("cp.async.commit_group;" ::: "memory")
#define CP_WAIT1()  asm volatile("cp.async.wait_group 1;" ::: "memory")
#define CP_WAIT0()  asm volatile("cp.async.wait_group 0;" ::: "memory")

// ---------------- P0: A->fp16, W2->fp16, baseT, zero logits ----------------
#define PREP_A 16384
#define PREP_W 256
__global__ void prep_kernel(const float4* __restrict__ A4, const float4* __restrict__ W24,
                            const float* __restrict__ hidden, const float* __restrict__ W1,
                            const float* __restrict__ b1, const float* __restrict__ b2) {
    int b = blockIdx.x, t = threadIdx.x;
    if (b < PREP_A) {
        #pragma unroll
        for (int k = 0; k < 4; ++k) {
            int i4 = b * 1024 + k * 256 + t;
            float4 v = A4[i4];
            ((__half2*)g_Af)[i4 * 2 + 0] = __halves2half2(__float2half(v.x), __float2half(v.y));
            ((__half2*)g_Af)[i4 * 2 + 1] = __halves2half2(__float2half(v.z), __float2half(v.w));
        }
    } else if (b < PREP_A + PREP_W) {
        int bb = b - PREP_A;
        #pragma unroll
        for (int k = 0; k < 4; ++k) {
            int i4 = bb * 1024 + k * 256 + t;
            float4 v = W24[i4];
            ((__half2*)g_W2f)[i4 * 2 + 0] = __halves2half2(__float2half(v.x), __float2half(v.y));
            ((__half2*)g_W2f)[i4 * 2 + 1] = __halves2half2(__float2half(v.z), __float2half(v.w));
        }
    } else {
        int e = b - (PREP_A + PREP_W);
        int w = t >> 5, ln = t & 31;
        if (t < 64) g_a[e * 64 + t] = 0.0f;
        const float* w1r = W1 + e * H_DIM;
        float bias = b1[e] + b2[e];
        for (int n = w; n < N_DIM; n += 8) {
            const float* hr = hidden + n * H_DIM;
            float acc = 0.0f;
            #pragma unroll 4
            for (int h = ln; h < H_DIM; h += 32) acc += hr[h] * w1r[h];
            #pragma unroll
            for (int o = 16; o; o >>= 1) acc += __shfl_xor_sync(0xffffffffu, acc, o);
            if (ln == 0) g_baseT[e * N_DIM + n] = acc + bias;
        }
    }
}

// ---------------- K1: fp16 mma.sync GEMM (64x32 warp tiles, 2 CTA/SM) ----------------
__global__ void __launch_bounds__(GT, 2) gemm_kernel(const float* __restrict__ W3) {
    extern __shared__ char smem_raw[];
    uint32_t base;
    asm("{ .reg .u64 t; cvta.to.shared.u64 t, %1; cvt.u32.u64 %0, t; }" : "=r"(base) : "l"(smem_raw));
    char* smem_al = smem_raw;

    const int tid = threadIdx.x;
    const int lane = tid & 31;
    const int wid = tid >> 5;
    const int wM = wid & 1;            // 2 x 64 rows
    const int wN = wid >> 1;           // 4 x 32 cols
    const int eBase = blockIdx.x * BN; // x fastest -> 8 CTAs share A tile in L2
    const int mBase = blockIdx.y * BM;

    float acc[4][4][4];
    #pragma unroll
    for (int i = 0; i < 4; i++)
        #pragma unroll
        for (int j = 0; j < 4; j++)
            #pragma unroll
            for (int k = 0; k < 4; k++) acc[i][j][k] = 0.0f;

    auto load_stage = [&](int s, int buf) {
        uint32_t sb = base + buf * STAGE_BYTES;
        int k0 = s * BK;
        #pragma unroll
        for (int i = 0; i < 4; i++) {   // A & B: 128 rows x 8 chunks of 16B each
            int idx = i * GT + tid, r = idx >> 3, c = idx & 7;
            cp16(sb + OFF_A + r * ROW_B + c * 16,
                 g_Af + (size_t)(mBase + r) * H_DIM + k0 + c * 8);
            cp16(sb + OFF_B + r * ROW_B + c * 16,
                 g_W2f + (size_t)(eBase + r) * H_DIM + k0 + c * 8);
        }
        CP_COMMIT();
    };

    auto compute = [&](int buf) {
        uint32_t sb = base + buf * STAGE_BYTES;
        uint32_t aA = sb + OFF_A, bB = sb + OFF_B;
        #pragma unroll
        for (int ks2 = 0; ks2 < 2; ks2++) {      // two k32 chunks
            uint32_t af[4][2][4];
            #pragma unroll
            for (int mt = 0; mt < 4; mt++)
                #pragma unroll
                for (int ku = 0; ku < 2; ku++) {
                    int row = wM * 64 + mt * 16 + (lane & 15);
                    uint32_t off = row * ROW_B + ks2 * 64 + ku * 32 + ((lane >> 4) * 16);
                    ldmx4(af[mt][ku], aA + off);
                }
            #pragma unroll
            for (int nt = 0; nt < 4; nt++) {
                uint32_t bf[4];
                int row = wN * 32 + nt * 8 + (lane & 7);
                uint32_t off = row * ROW_B + ks2 * 64 + ((lane >> 3) * 16);
                ldmx4(bf, bB + off);
                #pragma unroll
                for (int mt = 0; mt < 4; mt++) {
                    mma16816(acc[mt][nt], af[mt][0], bf[0], bf[1]);
                    mma16816(acc[mt][nt], af[mt][1], bf[2], bf[3]);
                }
            }
        }
    };

    load_stage(0, 0);
    load_stage(1, 1);
    #pragma unroll 1
    for (int kt = 0; kt < NKT; ++kt) {
        if (kt + 1 < NKT) CP_WAIT1(); else CP_WAIT0();
        __syncthreads();
        if (kt + 2 < NKT) load_stage(kt + 2, (kt + 2) % 3);
        compute(kt % 3);
    }
    __syncthreads();

    // ---- epilogue: logits partial over this e-slab ----
    float* sBase = (float*)smem_al;          // [128 e][32 n] = 16 KB
    float* sW3 = sBase + BN * 32;
    for (int idx = tid; idx < BN * 32; idx += GT) sBase[idx] = g_baseT[eBase * 32 + idx];
    if (tid < BN) sW3[tid] = W3[eBase + tid];
    __syncthreads();

    #pragma unroll
    for (int mt = 0; mt < 4; mt++)
        #pragma unroll
        for (int rp = 0; rp < 2; rp++) {
            int rloc = wM * 64 + mt * 16 + rp * 8 + (lane >> 2);
            int n = rloc & 31;
            float part = 0.0f;
            #pragma unroll
            for (int nt = 0; nt < 4; nt++) {
                int el = wN * 32 + nt * 8 + ((lane & 3) << 1);
                float p0 = acc[mt][nt][rp * 2 + 0] + sBase[el * 32 + n];
                float p1 = acc[mt][nt][rp * 2 + 1] + sBase[(el + 1) * 32 + n];
                part += sW3[el] * tanhf(p0) + sW3[el + 1] * tanhf(p1);
            }
            part += __shfl_xor_sync(0xffffffffu, part, 1);
            part += __shfl_xor_sync(0xffffffffu, part, 2);
            if ((lane & 3) == 0) atomicAdd(&g_a[mBase + rloc], part);
        }
}

// ---------------- K2: softmax over S per n; zeroes context region ----------------
__global__ void softmax_kernel(float* __restrict__ alpha, float* __restrict__ c) {
    int n = blockIdx.x, tid = threadIdx.x;
    ((float4*)(c + n * H_DIM))[tid] = make_float4(0.f, 0.f, 0.f, 0.f);
    float v[8], mx = -1e30f;
    #pragma unroll
    for (int i = 0; i < 8; i++) {
        v[i] = g_a[(i * 256 + tid) * N_DIM + n];
        mx = fmaxf(mx, v[i]);
    }
    #pragma unroll
    for (int o = 16; o; o >>= 1) mx = fmaxf(mx, __shfl_xor_sync(0xffffffffu, mx, o));
    __shared__ float sm[8];
    if ((tid & 31) == 0) sm[tid >> 5] = mx;
    __syncthreads();
    float bm = fmaxf(fmaxf(fmaxf(sm[0], sm[1]), fmaxf(sm[2], sm[3])),
                     fmaxf(fmaxf(sm[4], sm[5]), fmaxf(sm[6], sm[7])));
    float sum = 0.0f;
    #pragma unroll
    for (int i = 0; i < 8; i++) { v[i] = expf(v[i] - bm); sum += v[i]; }
    #pragma unroll
    for (int o = 16; o; o >>= 1) sum += __shfl_xor_sync(0xffffffffu, sum, o);
    __syncthreads();
    if ((tid & 31) == 0) sm[tid >> 5] = sum;
    __syncthreads();
    float inv = 1.0f / (sm[0] + sm[1] + sm[2] + sm[3] + sm[4] + sm[5] + sm[6] + sm[7]);
    #pragma unroll
    for (int i = 0; i < 8; i++) alpha[(i * 256 + tid) * N_DIM + n] = v[i] * inv;
}

// ---------------- K3: c[n][h] = sum_s alpha[s,n]*out_e[s,n,h] ----------------
__global__ void context_kernel(const float* __restrict__ out_e,
                               const float* __restrict__ alpha, float* __restrict__ c) {
    int n = blockIdx.x, sc = blockIdx.y, tid = threadIdx.x;
    const float4* p = (const float4*)out_e + (size_t)n * (H_DIM / 4) + tid;
    const size_t srow = (size_t)N_DIM * H_DIM / 4;
    float4 acc = make_float4(0.f, 0.f, 0.f, 0.f);
    int s0 = sc * 128;
    #pragma unroll 4
    for (int s = s0; s < s0 + 128; ++s) {
        float al = alpha[s * N_DIM + n];
        float4 x = p[s * srow];
        acc.x += al * x.x; acc.y += al * x.y; acc.z += al * x.z; acc.w += al * x.w;
    }
    float* dst = c + n * H_DIM + tid * 4;
    atomicAdd(dst + 0, acc.x); atomicAdd(dst + 1, acc.y);
    atomicAdd(dst + 2, acc.z); atomicAdd(dst + 3, acc.w);
}

// ---------------- launch ----------------
extern "C" void kernel_launch(void* const* d_in, const int* in_sizes, int n_in,
                              void* d_out, int out_size) {
    const float* out_e  = (const float*)d_in[0];
    const float* hidden = (const float*)d_in[1];
    const float* W1     = (const float*)d_in[2];
    const float* b1     = (const float*)d_in[3];
    const float* W2     = (const float*)d_in[4];
    const float* b2     = (const float*)d_in[5];
    const float* W3     = (const float*)d_in[6];
    // b3: softmax-invariant, unused.

    float* c_out = (float*)d_out;
    float* alpha_out = c_out + N_DIM * H_DIM;

    static int init = 0;
    if (!init) {
        cudaFuncSetAttribute(gemm_kernel, cudaFuncAttributeMaxDynamicSharedMemorySize, GEMM_SMEM);
        init = 1;
    }

    prep_kernel<<<PREP_A + PREP_W + E_DIM, 256>>>((const float4*)out_e, (const float4*)W2,
                                                  hidden, W1, b1, b2);
    gemm_kernel<<<dim3(E_DIM / BN, M_TOTAL / BM), GT, GEMM_SMEM>>>(W3);
    softmax_kernel<<<N_DIM, 256>>>(alpha_out, c_out);
    context_kernel<<<dim3(N_DIM, 16), 256>>>(out_e, alpha_out, c_out);
}

// round 16
// speedup vs baseline: 3.0732x; 1.0723x over previous
#include <cuda_runtime.h>
#include <cuda_fp16.h>
#include <math.h>
#include <stdint.h>

#define S_DIM 2048
#define N_DIM 32
#define H_DIM 1024
#define E_DIM 1024
#define M_TOTAL (S_DIM * N_DIM)

// ---------------- GEMM config ----------------
#define BM 128
#define BN 128
#define BK 64
#define NKT (H_DIM / BK)              // 16 k-stages
#define GT 256                         // 8 warps: 2 along M x 4 along N, warp tile 64x32
#define ROW_B 144                      // 64 halves (128B) + 16B pad -> conflict-free ldmatrix
#define OFF_A 0
#define OFF_B (BM * ROW_B)             // 18432
#define STAGE_BYTES (OFF_B + BN * ROW_B)   // 36864
#define GEMM_SMEM (3 * STAGE_BYTES)    // 110592 -> 2 CTAs/SM

// ---------------- device scratch ----------------
__device__ __align__(256) __half g_Af[M_TOTAL * H_DIM];   // 128 MB (A as fp16)
__device__ __align__(256) __half g_W2f[E_DIM * H_DIM];    // 2 MB
__device__ float g_baseT[E_DIM * N_DIM];                   // [e][n]
__device__ float g_a[M_TOTAL];

// ---------------- helpers ----------------
__device__ __forceinline__ void ldmx4(uint32_t* r, uint32_t addr) {
    asm volatile("ldmatrix.sync.aligned.m8n8.x4.shared.b16 {%0,%1,%2,%3}, [%4];"
                 : "=r"(r[0]), "=r"(r[1]), "=r"(r[2]), "=r"(r[3]) : "r"(addr));
}
__device__ __forceinline__ void mma16816(float* c, const uint32_t* a, uint32_t b0, uint32_t b1) {
    asm volatile("mma.sync.aligned.m16n8k16.row.col.f32.f16.f16.f32 "
                 "{%0,%1,%2,%3}, {%4,%5,%6,%7}, {%8,%9}, {%0,%1,%2,%3};"
                 : "+f"(c[0]), "+f"(c[1]), "+f"(c[2]), "+f"(c[3])
                 : "r"(a[0]), "r"(a[1]), "r"(a[2]), "r"(a[3]), "r"(b0), "r"(b1));
}
__device__ __forceinline__ void cp16(uint32_t dst, const void* src) {
    asm volatile("cp.async.cg.shared.global [%0], [%1], 16;" :: "r"(dst), "l"(src) : "memory");
}
#define CP_COMMIT() asm volatile("cp.async.commit_group;" ::: "memory")
#define CP_WAIT1()  asm volatile("cp.async.wait_group 1;" ::: "memory")
#define CP_WAIT0()  asm volatile("cp.async.wait_group 0;" ::: "memory")

// ---------------- P0: A->fp16, W2->fp16, baseT, zero logits ----------------
#define PREP_A 16384
#define PREP_W 256
__global__ void prep_kernel(const float4* __restrict__ A4, const float4* __restrict__ W24,
                            const float* __restrict__ hidden, const float* __restrict__ W1,
                            const float* __restrict__ b1, const float* __restrict__ b2) {
    int b = blockIdx.x, t = threadIdx.x;
    if (b < PREP_A) {
        #pragma unroll
        for (int k = 0; k < 4; ++k) {
            int i4 = b * 1024 + k * 256 + t;
            float4 v = A4[i4];
            ((__half2*)g_Af)[i4 * 2 + 0] = __halves2half2(__float2half(v.x), __float2half(v.y));
            ((__half2*)g_Af)[i4 * 2 + 1] = __halves2half2(__float2half(v.z), __float2half(v.w));
        }
    } else if (b < PREP_A + PREP_W) {
        int bb = b - PREP_A;
        #pragma unroll
        for (int k = 0; k < 4; ++k) {
            int i4 = bb * 1024 + k * 256 + t;
            float4 v = W24[i4];
            ((__half2*)g_W2f)[i4 * 2 + 0] = __halves2half2(__float2half(v.x), __float2half(v.y));
            ((__half2*)g_W2f)[i4 * 2 + 1] = __halves2half2(__float2half(v.z), __float2half(v.w));
        }
    } else {
        int e = b - (PREP_A + PREP_W);
        int w = t >> 5, ln = t & 31;
        if (t < 64) g_a[e * 64 + t] = 0.0f;
        const float* w1r = W1 + e * H_DIM;
        float bias = b1[e] + b2[e];
        for (int n = w; n < N_DIM; n += 8) {
            const float* hr = hidden + n * H_DIM;
            float acc = 0.0f;
            #pragma unroll 4
            for (int h = ln; h < H_DIM; h += 32) acc += hr[h] * w1r[h];
            #pragma unroll
            for (int o = 16; o; o >>= 1) acc += __shfl_xor_sync(0xffffffffu, acc, o);
            if (ln == 0) g_baseT[e * N_DIM + n] = acc + bias;
        }
    }
}

// ---------------- K1: fp16 mma.sync GEMM (64x32 warp tiles, 2 CTA/SM) ----------------
__global__ void __launch_bounds__(GT, 2) gemm_kernel(const float* __restrict__ W3) {
    extern __shared__ char smem_raw[];
    uint32_t base;
    asm("{ .reg .u64 t; cvta.to.shared.u64 t, %1; cvt.u32.u64 %0, t; }" : "=r"(base) : "l"(smem_raw));
    char* smem_al = smem_raw;

    const int tid = threadIdx.x;
    const int lane = tid & 31;
    const int wid = tid >> 5;
    const int wM = wid & 1;            // 2 x 64 rows
    const int wN = wid >> 1;           // 4 x 32 cols
    const int eBase = blockIdx.x * BN; // x fastest -> 8 CTAs share A tile in L2
    const int mBase = blockIdx.y * BM;

    float acc[4][4][4];
    #pragma unroll
    for (int i = 0; i < 4; i++)
        #pragma unroll
        for (int j = 0; j < 4; j++)
            #pragma unroll
            for (int k = 0; k < 4; k++) acc[i][j][k] = 0.0f;

    // per-thread load coords (hoisted)
    const int lr = tid >> 3, lc = tid & 7;
    const uint32_t ldst = lr * ROW_B + lc * 16;
    const __half* gA = g_Af + (size_t)(mBase + lr) * H_DIM + lc * 8;
    const __half* gB = g_W2f + (size_t)(eBase + lr) * H_DIM + lc * 8;

    auto load_stage = [&](int s, int buf) {
        uint32_t sb = base + buf * STAGE_BYTES;
        int k0 = s * BK;
        #pragma unroll
        for (int i = 0; i < 4; i++) {   // A & B: 128 rows x 8 chunks of 16B each
            cp16(sb + OFF_A + i * 32 * ROW_B + ldst, gA + (size_t)(i * 32) * H_DIM + k0);
            cp16(sb + OFF_B + i * 32 * ROW_B + ldst, gB + (size_t)(i * 32) * H_DIM + k0);
        }
        CP_COMMIT();
    };

    // compute one k32 half-chunk of buffer `buf`
    auto half_chunk = [&](int buf, int ks2) {
        uint32_t sb = base + buf * STAGE_BYTES;
        uint32_t aA = sb + OFF_A, bB = sb + OFF_B;
        uint32_t af[4][2][4];
        #pragma unroll
        for (int mt = 0; mt < 4; mt++)
            #pragma unroll
            for (int ku = 0; ku < 2; ku++) {
                int row = wM * 64 + mt * 16 + (lane & 15);
                uint32_t off = row * ROW_B + ks2 * 64 + ku * 32 + ((lane >> 4) * 16);
                ldmx4(af[mt][ku], aA + off);
            }
        #pragma unroll
        for (int nt = 0; nt < 4; nt++) {
            uint32_t bf[4];
            int row = wN * 32 + nt * 8 + (lane & 7);
            uint32_t off = row * ROW_B + ks2 * 64 + ((lane >> 3) * 16);
            ldmx4(bf, bB + off);
            #pragma unroll
            for (int mt = 0; mt < 4; mt++) {
                mma16816(acc[mt][nt], af[mt][0], bf[0], bf[1]);
                mma16816(acc[mt][nt], af[mt][1], bf[2], bf[3]);
            }
        }
    };

    // one pipeline step: wait stage kt, compute buf, inject next load mid-compute
    #define STEP(kt, buf) do { \
        if ((kt) + 1 < NKT) CP_WAIT1(); else CP_WAIT0(); \
        __syncthreads(); \
        half_chunk((buf), 0); \
        if ((kt) + 2 < NKT) load_stage((kt) + 2, ((buf) + 2) % 3); \
        half_chunk((buf), 1); \
    } while (0)

    load_stage(0, 0);
    load_stage(1, 1);
    STEP(0, 0);
    #pragma unroll 1
    for (int kt = 1; kt < NKT; kt += 3) {   // 15 iters: buf pattern 1,2,0 (compile-time)
        STEP(kt, 1);
        STEP(kt + 1, 2);
        STEP(kt + 2, 0);
    }
    #undef STEP
    __syncthreads();

    // ---- epilogue: logits partial over this e-slab ----
    float* sBase = (float*)smem_al;          // [128 e][32 n] = 16 KB
    float* sW3 = sBase + BN * 32;
    for (int idx = tid; idx < BN * 32; idx += GT) sBase[idx] = g_baseT[eBase * 32 + idx];
    if (tid < BN) sW3[tid] = W3[eBase + tid];
    __syncthreads();

    #pragma unroll
    for (int mt = 0; mt < 4; mt++)
        #pragma unroll
        for (int rp = 0; rp < 2; rp++) {
            int rloc = wM * 64 + mt * 16 + rp * 8 + (lane >> 2);
            int n = rloc & 31;
            float part = 0.0f;
            #pragma unroll
            for (int nt = 0; nt < 4; nt++) {
                int el = wN * 32 + nt * 8 + ((lane & 3) << 1);
                float p0 = acc[mt][nt][rp * 2 + 0] + sBase[el * 32 + n];
                float p1 = acc[mt][nt][rp * 2 + 1] + sBase[(el + 1) * 32 + n];
                part += sW3[el] * tanhf(p0) + sW3[el + 1] * tanhf(p1);
            }
            part += __shfl_xor_sync(0xffffffffu, part, 1);
            part += __shfl_xor_sync(0xffffffffu, part, 2);
            if ((lane & 3) == 0) atomicAdd(&g_a[mBase + rloc], part);
        }
}

// ---------------- K2: softmax over S per n; zeroes context region ----------------
__global__ void softmax_kernel(float* __restrict__ alpha, float* __restrict__ c) {
    int n = blockIdx.x, tid = threadIdx.x;
    ((float4*)(c + n * H_DIM))[tid] = make_float4(0.f, 0.f, 0.f, 0.f);
    float v[8], mx = -1e30f;
    #pragma unroll
    for (int i = 0; i < 8; i++) {
        v[i] = g_a[(i * 256 + tid) * N_DIM + n];
        mx = fmaxf(mx, v[i]);
    }
    #pragma unroll
    for (int o = 16; o; o >>= 1) mx = fmaxf(mx, __shfl_xor_sync(0xffffffffu, mx, o));
    __shared__ float sm[8];
    if ((tid & 31) == 0) sm[tid >> 5] = mx;
    __syncthreads();
    float bm = fmaxf(fmaxf(fmaxf(sm[0], sm[1]), fmaxf(sm[2], sm[3])),
                     fmaxf(fmaxf(sm[4], sm[5]), fmaxf(sm[6], sm[7])));
    float sum = 0.0f;
    #pragma unroll
    for (int i = 0; i < 8; i++) { v[i] = expf(v[i] - bm); sum += v[i]; }
    #pragma unroll
    for (int o = 16; o; o >>= 1) sum += __shfl_xor_sync(0xffffffffu, sum, o);
    __syncthreads();
    if ((tid & 31) == 0) sm[tid >> 5] = sum;
    __syncthreads();
    float inv = 1.0f / (sm[0] + sm[1] + sm[2] + sm[3] + sm[4] + sm[5] + sm[6] + sm[7]);
    #pragma unroll
    for (int i = 0; i < 8; i++) alpha[(i * 256 + tid) * N_DIM + n] = v[i] * inv;
}

// ---------------- K3: c[n][h] = sum_s alpha[s,n]*out_e[s,n,h] ----------------
__global__ void context_kernel(const float* __restrict__ out_e,
                               const float* __restrict__ alpha, float* __restrict__ c) {
    int n = blockIdx.x, sc = blockIdx.y, tid = threadIdx.x;
    const float4* p = (const float4*)out_e + (size_t)n * (H_DIM / 4) + tid;
    const size_t srow = (size_t)N_DIM * H_DIM / 4;
    float4 acc = make_float4(0.f, 0.f, 0.f, 0.f);
    int s0 = sc * 64;
    #pragma unroll 4
    for (int s = s0; s < s0 + 64; ++s) {
        float al = alpha[s * N_DIM + n];
        float4 x = p[s * srow];
        acc.x += al * x.x; acc.y += al * x.y; acc.z += al * x.z; acc.w += al * x.w;
    }
    float* dst = c + n * H_DIM + tid * 4;
    atomicAdd(dst + 0, acc.x); atomicAdd(dst + 1, acc.y);
    atomicAdd(dst + 2, acc.z); atomicAdd(dst + 3, acc.w);
}

// ---------------- launch ----------------
extern "C" void kernel_launch(void* const* d_in, const int* in_sizes, int n_in,
                              void* d_out, int out_size) {
    const float* out_e  = (const float*)d_in[0];
    const float* hidden = (const float*)d_in[1];
    const float* W1     = (const float*)d_in[2];
    const float* b1     = (const float*)d_in[3];
    const float* W2     = (const float*)d_in[4];
    const float* b2     = (const float*)d_in[5];
    const float* W3     = (const float*)d_in[6];
    // b3: softmax-invariant, unused.

    float* c_out = (float*)d_out;
    float* alpha_out = c_out + N_DIM * H_DIM;

    static int init = 0;
    if (!init) {
        cudaFuncSetAttribute(gemm_kernel, cudaFuncAttributeMaxDynamicSharedMemorySize, GEMM_SMEM);
        init = 1;
    }

    prep_kernel<<<PREP_A + PREP_W + E_DIM, 256>>>((const float4*)out_e, (const float4*)W2,
                                                  hidden, W1, b1, b2);
    gemm_kernel<<<dim3(E_DIM / BN, M_TOTAL / BM), GT, GEMM_SMEM>>>(W3);
    softmax_kernel<<<N_DIM, 256>>>(alpha_out, c_out);
    context_kernel<<<dim3(N_DIM, 32), 256>>>(out_e, alpha_out, c_out);
}